// round 1
// baseline (speedup 1.0000x reference)
#include <cuda_runtime.h>
#include <math.h>

#define BB    128
#define NSEQ  256
#define DD    512          // NODE
#define DEMB_ 256
#define KTOP  8
#define HID_  512
#define LABELS_ 19

// ---------------- scratch (device globals; no allocations) ----------------
__device__ float g_x[BB * NSEQ * DD];        // node features [B,N,512]
__device__ float g_xn[BB * NSEQ * DD];       // normalized x, then reused as x@qw
__device__ float g_adj[BB * NSEQ * NSEQ];    // sim, then adj
__device__ float g_comb[BB * NSEQ * DD];     // gcn_out + conv_out
__device__ float g_entcat[BB * 2 * DEMB_];
__device__ float g_vals[BB * NSEQ * KTOP];
__device__ int   g_idx[BB * NSEQ * KTOP];

// ---------------- embedding gather: x[:, :, 0:256] = emb[ids] ----------------
__global__ void k_embed(const int* __restrict__ ids, const float* __restrict__ emb) {
    int row = blockIdx.x;                       // b*N + n
    int id = ids[row];
    const float4* src = (const float4*)(emb + (size_t)id * DEMB_);
    float4* dst = (float4*)(g_x + (size_t)row * DD);
    dst[threadIdx.x] = src[threadIdx.x];        // 64 threads * float4 = 256 floats
}

// ---------------- entity masked-mean pooling ----------------
__global__ void k_entpool(const float* __restrict__ e1, const float* __restrict__ e2) {
    int b = blockIdx.x;
    int t = threadIdx.x;                        // 256 threads = DEMB
    __shared__ float m1[NSEQ], m2[NSEQ];
    __shared__ float c1s, c2s;
    m1[t] = e1[b * NSEQ + t];
    m2[t] = e2[b * NSEQ + t];
    __syncthreads();
    if (t == 0) {
        float a = 0.f, c = 0.f;
        for (int n = 0; n < NSEQ; n++) { a += m1[n]; c += m2[n]; }
        c1s = a; c2s = c;
    }
    __syncthreads();
    float s1 = 0.f, s2 = 0.f;
    const float* xb = g_x + (size_t)b * NSEQ * DD;
    for (int n = 0; n < NSEQ; n++) {
        float v = xb[(size_t)n * DD + t];       // seq part (d < 256)
        s1 += v * m1[n];
        s2 += v * m2[n];
    }
    g_entcat[b * 512 + t]       = s1 / (c1s + 1e-13f);
    g_entcat[b * 512 + 256 + t] = s2 / (c2s + 1e-13f);
}

// ---------------- ent = entcat @ ep_w + ep_b, broadcast into x[:, :, 256:512] ----------------
__global__ void k_entproj(const float* __restrict__ ep_w, const float* __restrict__ ep_b) {
    int b = blockIdx.x;
    int j = threadIdx.x;                        // 256
    __shared__ float ec[512];
    ec[j]       = g_entcat[b * 512 + j];
    ec[j + 256] = g_entcat[b * 512 + j + 256];
    __syncthreads();
    float acc = ep_b[j];
    for (int d = 0; d < 512; d++) acc += ec[d] * ep_w[d * DEMB_ + j];
    float* xb = g_x + (size_t)b * NSEQ * DD + DEMB_ + j;
    for (int n = 0; n < NSEQ; n++) xb[(size_t)n * DD] = acc;
}

// ---------------- row L2 normalize: xn = x / max(||x||, 1e-12) ----------------
__global__ void k_rownorm() {
    int row = blockIdx.x;                       // B*N rows
    int t = threadIdx.x;                        // 128 threads * float4 = 512
    const float4* xr = (const float4*)(g_x + (size_t)row * DD);
    float4 v = xr[t];
    float ss = v.x * v.x + v.y * v.y + v.z * v.z + v.w * v.w;
    #pragma unroll
    for (int o = 16; o > 0; o >>= 1) ss += __shfl_xor_sync(0xffffffffu, ss, o);
    __shared__ float ws[4];
    if ((t & 31) == 0) ws[t >> 5] = ss;
    __syncthreads();
    float tot = ws[0] + ws[1] + ws[2] + ws[3];
    float inv = 1.f / fmaxf(sqrtf(tot), 1e-12f);
    float4* o4 = (float4*)(g_xn + (size_t)row * DD);
    v.x *= inv; v.y *= inv; v.z *= inv; v.w *= inv;
    o4[t] = v;
}

// ---------------- sim[b] = xn[b] @ xn[b]^T   (256x256, K=512) ----------------
__global__ __launch_bounds__(256) void k_sim() {
    int b = blockIdx.z;
    int i0 = blockIdx.y * 64, j0 = blockIdx.x * 64;
    const float* A = g_xn + (size_t)b * NSEQ * DD;
    __shared__ float As[32][65], Bs[32][65];
    int tid = threadIdx.x;
    int tx = tid & 15, ty = tid >> 4;
    int lk = tid & 31, lr = tid >> 5;
    float c[4][4] = {};
    for (int kk = 0; kk < DD; kk += 32) {
        #pragma unroll
        for (int r = lr; r < 64; r += 8) {
            As[lk][r] = A[(size_t)(i0 + r) * DD + kk + lk];
            Bs[lk][r] = A[(size_t)(j0 + r) * DD + kk + lk];
        }
        __syncthreads();
        #pragma unroll
        for (int k = 0; k < 32; k++) {
            float a0 = As[k][ty], a1 = As[k][ty + 16], a2 = As[k][ty + 32], a3 = As[k][ty + 48];
            float b0 = Bs[k][tx], b1 = Bs[k][tx + 16], b2 = Bs[k][tx + 32], b3 = Bs[k][tx + 48];
            c[0][0] += a0 * b0; c[0][1] += a0 * b1; c[0][2] += a0 * b2; c[0][3] += a0 * b3;
            c[1][0] += a1 * b0; c[1][1] += a1 * b1; c[1][2] += a1 * b2; c[1][3] += a1 * b3;
            c[2][0] += a2 * b0; c[2][1] += a2 * b1; c[2][2] += a2 * b2; c[2][3] += a2 * b3;
            c[3][0] += a3 * b0; c[3][1] += a3 * b1; c[3][2] += a3 * b2; c[3][3] += a3 * b3;
        }
        __syncthreads();
    }
    float* C = g_adj + (size_t)b * NSEQ * NSEQ;
    #pragma unroll
    for (int u = 0; u < 4; u++)
        #pragma unroll
        for (int v2 = 0; v2 < 4; v2++)
            C[(size_t)(i0 + ty + 16 * u) * NSEQ + j0 + tx + 16 * v2] = c[u][v2];
}

// ---------------- per-row top-8 (stable-by-index like jax.lax.top_k) ----------------
__global__ void k_topk() {
    int row = blockIdx.x * blockDim.x + threadIdx.x;
    if (row >= BB * NSEQ) return;
    const float* s = g_adj + (size_t)row * NSEQ;
    float v[KTOP]; int id[KTOP];
    #pragma unroll
    for (int k = 0; k < KTOP; k++) { v[k] = -1e30f; id[k] = -1; }
    for (int m = 0; m < NSEQ; m++) {
        float x = s[m];
        if (x > v[KTOP - 1]) {
            int p = KTOP - 1;
            while (p > 0 && v[p - 1] < x) { v[p] = v[p - 1]; id[p] = id[p - 1]; p--; }
            v[p] = x; id[p] = m;
        }
    }
    #pragma unroll
    for (int k = 0; k < KTOP; k++) {
        g_vals[row * KTOP + k] = v[k];
        g_idx[row * KTOP + k]  = id[k];
    }
}

// ---------------- zero adj ----------------
__global__ void k_zero_adj() {
    int i = blockIdx.x * blockDim.x + threadIdx.x;
    int n4 = BB * NSEQ * NSEQ / 4;
    if (i < n4) ((float4*)g_adj)[i] = make_float4(0.f, 0.f, 0.f, 0.f);
}

// ---------------- adj = (mask + mask^T)/2 via atomic scatter ----------------
__global__ void k_adjbuild() {
    int t = blockIdx.x * blockDim.x + threadIdx.x;
    if (t >= BB * NSEQ * KTOP) return;
    int row = t / KTOP;
    int b = row / NSEQ, n = row % NSEQ;
    float v = 0.5f * g_vals[t];
    int m = g_idx[t];
    float* adjb = g_adj + (size_t)b * NSEQ * NSEQ;
    atomicAdd(&adjb[n * NSEQ + m], v);
    atomicAdd(&adjb[m * NSEQ + n], v);
}

// ---------------- xqw = x @ quantize(gcn_w[i])   M=32768, N=512, K=512 ----------------
__global__ __launch_bounds__(256) void k_xqw(const float* __restrict__ W) {
    int i0 = blockIdx.y * 64, j0 = blockIdx.x * 64;
    __shared__ float As[32][65], Bs[32][64];
    int tid = threadIdx.x;
    int tx = tid & 15, ty = tid >> 4;
    int lkA = tid & 31, lrA = tid >> 5;
    int ljB = tid & 63, lkB = tid >> 6;
    float c[4][4] = {};
    for (int kk = 0; kk < DD; kk += 32) {
        #pragma unroll
        for (int r = lrA; r < 64; r += 8)
            As[lkA][r] = g_x[(size_t)(i0 + r) * DD + kk + lkA];
        #pragma unroll
        for (int k = lkB; k < 32; k += 4) {
            float w = W[(size_t)(kk + k) * DD + j0 + ljB];
            Bs[k][ljB] = (w > 0.1f) ? 0.1f : ((w < -0.1f) ? -0.1f : 0.f);
        }
        __syncthreads();
        #pragma unroll
        for (int k = 0; k < 32; k++) {
            float a0 = As[k][ty], a1 = As[k][ty + 16], a2 = As[k][ty + 32], a3 = As[k][ty + 48];
            float b0 = Bs[k][tx], b1 = Bs[k][tx + 16], b2 = Bs[k][tx + 32], b3 = Bs[k][tx + 48];
            c[0][0] += a0 * b0; c[0][1] += a0 * b1; c[0][2] += a0 * b2; c[0][3] += a0 * b3;
            c[1][0] += a1 * b0; c[1][1] += a1 * b1; c[1][2] += a1 * b2; c[1][3] += a1 * b3;
            c[2][0] += a2 * b0; c[2][1] += a2 * b1; c[2][2] += a2 * b2; c[2][3] += a2 * b3;
            c[3][0] += a3 * b0; c[3][1] += a3 * b1; c[3][2] += a3 * b2; c[3][3] += a3 * b3;
        }
        __syncthreads();
    }
    #pragma unroll
    for (int u = 0; u < 4; u++)
        #pragma unroll
        for (int v2 = 0; v2 < 4; v2++)
            g_xn[(size_t)(i0 + ty + 16 * u) * DD + j0 + tx + 16 * v2] = c[u][v2];
}

// ---------------- gcn_out = relu(adj[b] @ xqw[b] + bias)   256x512, K=256 ----------------
__global__ __launch_bounds__(256) void k_gcn(const float* __restrict__ bias) {
    int b = blockIdx.z;
    int i0 = blockIdx.y * 64, j0 = blockIdx.x * 64;
    const float* A  = g_adj + (size_t)b * NSEQ * NSEQ;
    const float* Bm = g_xn  + (size_t)b * NSEQ * DD;
    __shared__ float As[32][65], Bs[32][64];
    int tid = threadIdx.x;
    int tx = tid & 15, ty = tid >> 4;
    int lkA = tid & 31, lrA = tid >> 5;
    int ljB = tid & 63, lkB = tid >> 6;
    float c[4][4] = {};
    for (int kk = 0; kk < NSEQ; kk += 32) {
        #pragma unroll
        for (int r = lrA; r < 64; r += 8)
            As[lkA][r] = A[(size_t)(i0 + r) * NSEQ + kk + lkA];
        #pragma unroll
        for (int k = lkB; k < 32; k += 4)
            Bs[k][ljB] = Bm[(size_t)(kk + k) * DD + j0 + ljB];
        __syncthreads();
        #pragma unroll
        for (int k = 0; k < 32; k++) {
            float a0 = As[k][ty], a1 = As[k][ty + 16], a2 = As[k][ty + 32], a3 = As[k][ty + 48];
            float b0 = Bs[k][tx], b1 = Bs[k][tx + 16], b2 = Bs[k][tx + 32], b3 = Bs[k][tx + 48];
            c[0][0] += a0 * b0; c[0][1] += a0 * b1; c[0][2] += a0 * b2; c[0][3] += a0 * b3;
            c[1][0] += a1 * b0; c[1][1] += a1 * b1; c[1][2] += a1 * b2; c[1][3] += a1 * b3;
            c[2][0] += a2 * b0; c[2][1] += a2 * b1; c[2][2] += a2 * b2; c[2][3] += a2 * b3;
            c[3][0] += a3 * b0; c[3][1] += a3 * b1; c[3][2] += a3 * b2; c[3][3] += a3 * b3;
        }
        __syncthreads();
    }
    float* C = g_comb + (size_t)b * NSEQ * DD;
    #pragma unroll
    for (int u = 0; u < 4; u++)
        #pragma unroll
        for (int v2 = 0; v2 < 4; v2++) {
            int j = j0 + tx + 16 * v2;
            float r = c[u][v2] + bias[j];
            C[(size_t)(i0 + ty + 16 * u) * DD + j] = fmaxf(r, 0.f);
        }
}

// ---------------- fused conv1(1->32,3x3) -> BN -> ReLU -> conv2(32->1,3x3); combined += out ----------------
__global__ __launch_bounds__(256) void k_conv(const float* __restrict__ c1w, const float* __restrict__ c1b,
                                              const float* __restrict__ bng, const float* __restrict__ bnb,
                                              const float* __restrict__ c2w, const float* __restrict__ c2b) {
    __shared__ float xt[20][21];
    __shared__ float hs[32][18][18];
    __shared__ float w1[32][9], w2[32][9], sc[32], tc[32];
    int b = blockIdx.z;
    int oy0 = blockIdx.y * 16, ox0 = blockIdx.x * 16;
    int t = threadIdx.x;
    if (t < 32) {
        float s = bng[t] * rsqrtf(1.f + 1e-5f);
        sc[t] = s;
        tc[t] = c1b[t] * s + bnb[t];
    }
    for (int i = t; i < 288; i += 256) {
        w1[i / 9][i % 9] = c1w[i];
        w2[i / 9][i % 9] = c2w[i];
    }
    const float* xb = g_x + (size_t)b * NSEQ * DD;
    for (int i = t; i < 400; i += 256) {
        int ly = i / 20, lx = i % 20;
        int gy = oy0 - 2 + ly, gx = ox0 - 2 + lx;
        float v = 0.f;
        if (gy >= 0 && gy < NSEQ && gx >= 0 && gx < DD) v = xb[(size_t)gy * DD + gx];
        xt[ly][lx] = v;
    }
    __syncthreads();
    // h on (tile+1 halo): 18x18 per channel; OUTSIDE-IMAGE h must be ZERO (conv2 zero-pads h)
    for (int i = t; i < 32 * 18 * 18; i += 256) {
        int c = i / 324, r = i % 324;
        int ly = r / 18, lx = r % 18;
        int gy = oy0 - 1 + ly, gx = ox0 - 1 + lx;
        float hv = 0.f;
        if (gy >= 0 && gy < NSEQ && gx >= 0 && gx < DD) {
            float a = 0.f;
            #pragma unroll
            for (int dy = 0; dy < 3; dy++)
                #pragma unroll
                for (int dx = 0; dx < 3; dx++)
                    a += xt[ly + dy][lx + dx] * w1[c][dy * 3 + dx];
            hv = fmaxf(a * sc[c] + tc[c], 0.f);
        }
        hs[c][ly][lx] = hv;
    }
    __syncthreads();
    int oy = t >> 4, ox = t & 15;
    float acc = c2b[0];
    #pragma unroll 4
    for (int c = 0; c < 32; c++) {
        #pragma unroll
        for (int dy = 0; dy < 3; dy++)
            #pragma unroll
            for (int dx = 0; dx < 3; dx++)
                acc += hs[c][oy + dy][ox + dx] * w2[c][dy * 3 + dx];
    }
    g_comb[(size_t)b * NSEQ * DD + (size_t)(oy0 + oy) * DD + ox0 + ox] += acc;
}

// ---------------- gate + residual mix, in place into x ----------------
__global__ void k_gate(const float* __restrict__ gw, const float* __restrict__ gb) {
    int row = blockIdx.x;
    int t = threadIdx.x;                        // 256
    size_t off = (size_t)row * DD;
    float x1 = g_x[off + t],       x2 = g_x[off + t + 256];
    float c1 = g_comb[off + t],    c2 = g_comb[off + t + 256];
    float p = x1 * gw[t] + x2 * gw[t + 256] + c1 * gw[512 + t] + c2 * gw[768 + t];
    #pragma unroll
    for (int o = 16; o > 0; o >>= 1) p += __shfl_xor_sync(0xffffffffu, p, o);
    __shared__ float ws[8];
    if ((t & 31) == 0) ws[t >> 5] = p;
    __syncthreads();
    float tot = ws[0] + ws[1] + ws[2] + ws[3] + ws[4] + ws[5] + ws[6] + ws[7];
    float g = 1.f / (1.f + expf(-(tot + gb[0])));
    g_x[off + t]       = g * x1 + (1.f - g) * c1;
    g_x[off + t + 256] = g * x2 + (1.f - g) * c2;
}

// ---------------- mean pool + 2-layer classifier ----------------
__global__ void k_cls(const float* __restrict__ w1, const float* __restrict__ b1,
                      const float* __restrict__ w2, const float* __restrict__ b2,
                      float* __restrict__ out) {
    int b = blockIdx.x;
    int t = threadIdx.x;                        // 512
    __shared__ float pooled[512], h1[512];
    float s = 0.f;
    const float* xb = g_x + (size_t)b * NSEQ * DD;
    for (int n = 0; n < NSEQ; n++) s += xb[(size_t)n * DD + t];
    pooled[t] = s * (1.f / NSEQ);
    __syncthreads();
    float a = b1[t];
    for (int d = 0; d < 512; d++) a += pooled[d] * w1[d * 512 + t];
    h1[t] = fmaxf(a, 0.f);
    __syncthreads();
    if (t < LABELS_) {
        float a2 = b2[t];
        for (int d = 0; d < 512; d++) a2 += h1[d] * w2[d * LABELS_ + t];
        out[b * LABELS_ + t] = a2;
    }
}

// ---------------- launch ----------------
extern "C" void kernel_launch(void* const* d_in, const int* in_sizes, int n_in,
                              void* d_out, int out_size) {
    const int*   ids   = (const int*)  d_in[0];
    const float* e1    = (const float*)d_in[1];
    const float* e2    = (const float*)d_in[2];
    const float* emb   = (const float*)d_in[3];
    const float* ep_w  = (const float*)d_in[4];
    const float* ep_b  = (const float*)d_in[5];
    const float* gcn_w = (const float*)d_in[6];
    const float* gcn_b = (const float*)d_in[7];
    const float* c1w   = (const float*)d_in[8];
    const float* c1b   = (const float*)d_in[9];
    const float* bng   = (const float*)d_in[10];
    const float* bnb   = (const float*)d_in[11];
    const float* c2w   = (const float*)d_in[12];
    const float* c2b   = (const float*)d_in[13];
    const float* gw    = (const float*)d_in[14];
    const float* gb    = (const float*)d_in[15];
    const float* clw1  = (const float*)d_in[16];
    const float* clb1  = (const float*)d_in[17];
    const float* clw2  = (const float*)d_in[18];
    const float* clb2  = (const float*)d_in[19];
    float* out = (float*)d_out;

    k_embed<<<BB * NSEQ, 64>>>(ids, emb);
    k_entpool<<<BB, 256>>>(e1, e2);
    k_entproj<<<BB, 256>>>(ep_w, ep_b);

    for (int i = 0; i < 2; i++) {
        k_rownorm<<<BB * NSEQ, 128>>>();
        k_sim<<<dim3(4, 4, BB), 256>>>();
        k_topk<<<(BB * NSEQ + 127) / 128, 128>>>();
        k_zero_adj<<<(BB * NSEQ * NSEQ / 4 + 255) / 256, 256>>>();
        k_adjbuild<<<(BB * NSEQ * KTOP + 255) / 256, 256>>>();
        k_xqw<<<dim3(8, 512), 256>>>(gcn_w + (size_t)i * DD * DD);
        k_gcn<<<dim3(8, 4, BB), 256>>>(gcn_b + i * DD);
        k_conv<<<dim3(32, 16, BB), 256>>>(c1w + i * 288, c1b + i * 32,
                                          bng + i * 32, bnb + i * 32,
                                          c2w + i * 288, c2b + i);
        k_gate<<<BB * NSEQ, 256>>>(gw, gb);
    }
    k_cls<<<BB, 512>>>(clw1, clb1, clw2, clb2, out);
}

// round 2
// speedup vs baseline: 1.0953x; 1.0953x over previous
#include <cuda_runtime.h>
#include <math.h>

#define BB    128
#define NSEQ  256
#define DD    512          // NODE
#define DEMB_ 256
#define KTOP  8
#define LABELS_ 19

// ---------------- scratch (device globals; no allocations) ----------------
__device__ float g_x[BB * NSEQ * DD];        // node features [B,N,512]
__device__ float g_xn[BB * NSEQ * DD];       // normalized x, then reused as x@qw
__device__ float g_adj[BB * NSEQ * NSEQ];    // sim, then adj
__device__ float g_comb[BB * NSEQ * DD];     // gcn_out + conv_out
__device__ float g_entcat[BB * 2 * DEMB_];
__device__ float g_vals[BB * NSEQ * KTOP];
__device__ int   g_idx[BB * NSEQ * KTOP];

// ---------------- tf32 helpers ----------------
__device__ __forceinline__ unsigned f2tf(float f) {
    unsigned u;
    asm("cvt.rna.tf32.f32 %0, %1;" : "=r"(u) : "f"(f));
    return u;
}
__device__ __forceinline__ void mma_tf32(float* d, const unsigned* a, const unsigned* b) {
    asm volatile(
        "mma.sync.aligned.m16n8k8.row.col.f32.tf32.tf32.f32 "
        "{%0,%1,%2,%3}, {%4,%5,%6,%7}, {%8,%9}, {%0,%1,%2,%3};"
        : "+f"(d[0]), "+f"(d[1]), "+f"(d[2]), "+f"(d[3])
        : "r"(a[0]), "r"(a[1]), "r"(a[2]), "r"(a[3]), "r"(b[0]), "r"(b[1]));
}

// ---------------- embedding gather ----------------
__global__ void k_embed(const int* __restrict__ ids, const float* __restrict__ emb) {
    int row = blockIdx.x;
    int id = ids[row];
    const float4* src = (const float4*)(emb + (size_t)id * DEMB_);
    float4* dst = (float4*)(g_x + (size_t)row * DD);
    dst[threadIdx.x] = src[threadIdx.x];
}

// ---------------- entity masked-mean pooling ----------------
__global__ void k_entpool(const float* __restrict__ e1, const float* __restrict__ e2) {
    int b = blockIdx.x;
    int t = threadIdx.x;
    __shared__ float m1[NSEQ], m2[NSEQ];
    __shared__ float c1s, c2s;
    m1[t] = e1[b * NSEQ + t];
    m2[t] = e2[b * NSEQ + t];
    __syncthreads();
    if (t == 0) {
        float a = 0.f, c = 0.f;
        for (int n = 0; n < NSEQ; n++) { a += m1[n]; c += m2[n]; }
        c1s = a; c2s = c;
    }
    __syncthreads();
    float s1 = 0.f, s2 = 0.f;
    const float* xb = g_x + (size_t)b * NSEQ * DD;
    for (int n = 0; n < NSEQ; n++) {
        float v = xb[(size_t)n * DD + t];
        s1 += v * m1[n];
        s2 += v * m2[n];
    }
    g_entcat[b * 512 + t]       = s1 / (c1s + 1e-13f);
    g_entcat[b * 512 + 256 + t] = s2 / (c2s + 1e-13f);
}

// ---------------- ent = entcat @ ep_w + ep_b, broadcast ----------------
__global__ void k_entproj(const float* __restrict__ ep_w, const float* __restrict__ ep_b) {
    int b = blockIdx.x;
    int j = threadIdx.x;
    __shared__ float ec[512];
    ec[j]       = g_entcat[b * 512 + j];
    ec[j + 256] = g_entcat[b * 512 + j + 256];
    __syncthreads();
    float acc = ep_b[j];
    for (int d = 0; d < 512; d++) acc += ec[d] * ep_w[d * DEMB_ + j];
    float* xb = g_x + (size_t)b * NSEQ * DD + DEMB_ + j;
    for (int n = 0; n < NSEQ; n++) xb[(size_t)n * DD] = acc;
}

// ---------------- row L2 normalize ----------------
__global__ void k_rownorm() {
    int row = blockIdx.x;
    int t = threadIdx.x;
    const float4* xr = (const float4*)(g_x + (size_t)row * DD);
    float4 v = xr[t];
    float ss = v.x * v.x + v.y * v.y + v.z * v.z + v.w * v.w;
    #pragma unroll
    for (int o = 16; o > 0; o >>= 1) ss += __shfl_xor_sync(0xffffffffu, ss, o);
    __shared__ float ws[4];
    if ((t & 31) == 0) ws[t >> 5] = ss;
    __syncthreads();
    float tot = ws[0] + ws[1] + ws[2] + ws[3];
    float inv = 1.f / fmaxf(sqrtf(tot), 1e-12f);
    float4* o4 = (float4*)(g_xn + (size_t)row * DD);
    v.x *= inv; v.y *= inv; v.z *= inv; v.w *= inv;
    o4[t] = v;
}

// ---------------- sim = xn @ xn^T via 3xTF32 MMA (fp32-exact) ----------------
// tile 128x64, 8 warps (4x2), warp tile 32x32
__global__ __launch_bounds__(256) void k_sim_mma() {
    int b = blockIdx.z;
    int i0 = blockIdx.y * 128, j0 = blockIdx.x * 64;
    const float* A = g_xn + (size_t)b * NSEQ * DD;
    __shared__ unsigned Ah[128][20], Al[128][20];
    __shared__ unsigned Bh[16][72], Bl[16][72];
    int t = threadIdx.x;
    int lane = t & 31, wid = t >> 5;
    int wm = wid >> 1, wn = wid & 1;
    int g = lane >> 2, tig = lane & 3;
    float acc[2][4][4];
    #pragma unroll
    for (int a = 0; a < 2; a++)
        #pragma unroll
        for (int n = 0; n < 4; n++)
            #pragma unroll
            for (int e = 0; e < 4; e++) acc[a][n][e] = 0.f;

    for (int kk = 0; kk < DD; kk += 16) {
        // stage A: 128 rows x 16 k, hi/lo
        #pragma unroll
        for (int q = 0; q < 2; q++) {
            int idx = t + q * 256;
            int row = idx >> 2, j = idx & 3;
            float4 xv = *(const float4*)(A + (size_t)(i0 + row) * DD + kk + j * 4);
            uint4 h, l;
            h.x = f2tf(xv.x); l.x = f2tf(xv.x - __uint_as_float(h.x));
            h.y = f2tf(xv.y); l.y = f2tf(xv.y - __uint_as_float(h.y));
            h.z = f2tf(xv.z); l.z = f2tf(xv.z - __uint_as_float(h.z));
            h.w = f2tf(xv.w); l.w = f2tf(xv.w - __uint_as_float(h.w));
            *(uint4*)&Ah[row][j * 4] = h;
            *(uint4*)&Al[row][j * 4] = l;
        }
        // stage B (transposed rows j0..j0+63): 64 n x 16 k
        {
            int n = t >> 2, j = t & 3;
            float4 xv = *(const float4*)(A + (size_t)(j0 + n) * DD + kk + j * 4);
            float f[4] = {xv.x, xv.y, xv.z, xv.w};
            #pragma unroll
            for (int e = 0; e < 4; e++) {
                unsigned h = f2tf(f[e]);
                Bh[j * 4 + e][n] = h;
                Bl[j * 4 + e][n] = f2tf(f[e] - __uint_as_float(h));
            }
        }
        __syncthreads();
        #pragma unroll
        for (int ks = 0; ks < 2; ks++) {
            int k0 = ks * 8;
            unsigned ah[2][4], al[2][4], bh[4][2], bl[4][2];
            #pragma unroll
            for (int mt = 0; mt < 2; mt++) {
                int r = wm * 32 + mt * 16 + g;
                ah[mt][0] = Ah[r][k0 + tig];     ah[mt][1] = Ah[r + 8][k0 + tig];
                ah[mt][2] = Ah[r][k0 + tig + 4]; ah[mt][3] = Ah[r + 8][k0 + tig + 4];
                al[mt][0] = Al[r][k0 + tig];     al[mt][1] = Al[r + 8][k0 + tig];
                al[mt][2] = Al[r][k0 + tig + 4]; al[mt][3] = Al[r + 8][k0 + tig + 4];
            }
            #pragma unroll
            for (int nt = 0; nt < 4; nt++) {
                int n = wn * 32 + nt * 8 + g;
                bh[nt][0] = Bh[k0 + tig][n]; bh[nt][1] = Bh[k0 + tig + 4][n];
                bl[nt][0] = Bl[k0 + tig][n]; bl[nt][1] = Bl[k0 + tig + 4][n];
            }
            #pragma unroll
            for (int mt = 0; mt < 2; mt++)
                #pragma unroll
                for (int nt = 0; nt < 4; nt++) {
                    mma_tf32(acc[mt][nt], ah[mt], bh[nt]);
                    mma_tf32(acc[mt][nt], ah[mt], bl[nt]);
                    mma_tf32(acc[mt][nt], al[mt], bh[nt]);
                }
        }
        __syncthreads();
    }
    float* C = g_adj + (size_t)b * NSEQ * NSEQ;
    #pragma unroll
    for (int mt = 0; mt < 2; mt++)
        #pragma unroll
        for (int nt = 0; nt < 4; nt++) {
            int r = i0 + wm * 32 + mt * 16 + g;
            int c = j0 + wn * 32 + nt * 8 + tig * 2;
            C[(size_t)r * NSEQ + c]           = acc[mt][nt][0];
            C[(size_t)r * NSEQ + c + 1]       = acc[mt][nt][1];
            C[(size_t)(r + 8) * NSEQ + c]     = acc[mt][nt][2];
            C[(size_t)(r + 8) * NSEQ + c + 1] = acc[mt][nt][3];
        }
}

// ---------------- top-8 with coalesced smem staging ----------------
__global__ __launch_bounds__(128) void k_topk() {
    __shared__ float sh[128][36];
    int rb = blockIdx.x * 128;
    int t = threadIdx.x;
    float v[KTOP]; int id[KTOP];
    #pragma unroll
    for (int k = 0; k < KTOP; k++) { v[k] = -1e30f; id[k] = -1; }
    for (int ch = 0; ch < 8; ch++) {
        __syncthreads();
        for (int q = t; q < 1024; q += 128) {
            int row = q >> 3, c4 = q & 7;
            float4 x = *(const float4*)(g_adj + (size_t)(rb + row) * NSEQ + ch * 32 + c4 * 4);
            *(float4*)&sh[row][c4 * 4] = x;
        }
        __syncthreads();
        #pragma unroll 4
        for (int c = 0; c < 32; c++) {
            float x = sh[t][c];
            if (x > v[KTOP - 1]) {
                int m = ch * 32 + c;
                int p = KTOP - 1;
                while (p > 0 && v[p - 1] < x) { v[p] = v[p - 1]; id[p] = id[p - 1]; p--; }
                v[p] = x; id[p] = m;
            }
        }
    }
    int row = rb + t;
    #pragma unroll
    for (int k = 0; k < KTOP; k++) {
        g_vals[row * KTOP + k] = v[k];
        g_idx[row * KTOP + k]  = id[k];
    }
}

// ---------------- zero adj ----------------
__global__ void k_zero_adj() {
    int i = blockIdx.x * blockDim.x + threadIdx.x;
    int n4 = BB * NSEQ * NSEQ / 4;
    if (i < n4) ((float4*)g_adj)[i] = make_float4(0.f, 0.f, 0.f, 0.f);
}

// ---------------- adj = (mask + mask^T)/2 via atomic scatter ----------------
__global__ void k_adjbuild() {
    int t = blockIdx.x * blockDim.x + threadIdx.x;
    if (t >= BB * NSEQ * KTOP) return;
    int row = t / KTOP;
    int b = row / NSEQ, n = row % NSEQ;
    float v = 0.5f * g_vals[t];
    int m = g_idx[t];
    float* adjb = g_adj + (size_t)b * NSEQ * NSEQ;
    atomicAdd(&adjb[n * NSEQ + m], v);
    atomicAdd(&adjb[m * NSEQ + n], v);
}

// ---------------- xqw = x @ sign(W) * 0.1 via 2xTF32 MMA (x split, W exact) ----------------
__global__ __launch_bounds__(256) void k_xqw_mma(const float* __restrict__ W) {
    int i0 = blockIdx.y * 128, j0 = blockIdx.x * 64;
    __shared__ unsigned Ah[128][20], Al[128][20];
    __shared__ unsigned Bs[16][72];
    int t = threadIdx.x;
    int lane = t & 31, wid = t >> 5;
    int wm = wid >> 1, wn = wid & 1;
    int g = lane >> 2, tig = lane & 3;
    float acc[2][4][4];
    #pragma unroll
    for (int a = 0; a < 2; a++)
        #pragma unroll
        for (int n = 0; n < 4; n++)
            #pragma unroll
            for (int e = 0; e < 4; e++) acc[a][n][e] = 0.f;

    for (int kk = 0; kk < DD; kk += 16) {
        #pragma unroll
        for (int q = 0; q < 2; q++) {
            int idx = t + q * 256;
            int row = idx >> 2, j = idx & 3;
            float4 xv = *(const float4*)(g_x + (size_t)(i0 + row) * DD + kk + j * 4);
            uint4 h, l;
            h.x = f2tf(xv.x); l.x = f2tf(xv.x - __uint_as_float(h.x));
            h.y = f2tf(xv.y); l.y = f2tf(xv.y - __uint_as_float(h.y));
            h.z = f2tf(xv.z); l.z = f2tf(xv.z - __uint_as_float(h.z));
            h.w = f2tf(xv.w); l.w = f2tf(xv.w - __uint_as_float(h.w));
            *(uint4*)&Ah[row][j * 4] = h;
            *(uint4*)&Al[row][j * 4] = l;
        }
        {
            int k = t >> 4, n4 = t & 15;
            float4 w = *(const float4*)(W + (size_t)(kk + k) * DD + j0 + n4 * 4);
            uint4 q;
            q.x = __float_as_uint((w.x > 0.1f) ? 1.f : ((w.x < -0.1f) ? -1.f : 0.f));
            q.y = __float_as_uint((w.y > 0.1f) ? 1.f : ((w.y < -0.1f) ? -1.f : 0.f));
            q.z = __float_as_uint((w.z > 0.1f) ? 1.f : ((w.z < -0.1f) ? -1.f : 0.f));
            q.w = __float_as_uint((w.w > 0.1f) ? 1.f : ((w.w < -0.1f) ? -1.f : 0.f));
            *(uint4*)&Bs[k][n4 * 4] = q;
        }
        __syncthreads();
        #pragma unroll
        for (int ks = 0; ks < 2; ks++) {
            int k0 = ks * 8;
            unsigned ah[2][4], al[2][4], bs[4][2];
            #pragma unroll
            for (int mt = 0; mt < 2; mt++) {
                int r = wm * 32 + mt * 16 + g;
                ah[mt][0] = Ah[r][k0 + tig];     ah[mt][1] = Ah[r + 8][k0 + tig];
                ah[mt][2] = Ah[r][k0 + tig + 4]; ah[mt][3] = Ah[r + 8][k0 + tig + 4];
                al[mt][0] = Al[r][k0 + tig];     al[mt][1] = Al[r + 8][k0 + tig];
                al[mt][2] = Al[r][k0 + tig + 4]; al[mt][3] = Al[r + 8][k0 + tig + 4];
            }
            #pragma unroll
            for (int nt = 0; nt < 4; nt++) {
                int n = wn * 32 + nt * 8 + g;
                bs[nt][0] = Bs[k0 + tig][n]; bs[nt][1] = Bs[k0 + tig + 4][n];
            }
            #pragma unroll
            for (int mt = 0; mt < 2; mt++)
                #pragma unroll
                for (int nt = 0; nt < 4; nt++) {
                    mma_tf32(acc[mt][nt], ah[mt], bs[nt]);
                    mma_tf32(acc[mt][nt], al[mt], bs[nt]);
                }
        }
        __syncthreads();
    }
    #pragma unroll
    for (int mt = 0; mt < 2; mt++)
        #pragma unroll
        for (int nt = 0; nt < 4; nt++) {
            int r = i0 + wm * 32 + mt * 16 + g;
            int c = j0 + wn * 32 + nt * 8 + tig * 2;
            g_xn[(size_t)r * DD + c]           = 0.1f * acc[mt][nt][0];
            g_xn[(size_t)r * DD + c + 1]       = 0.1f * acc[mt][nt][1];
            g_xn[(size_t)(r + 8) * DD + c]     = 0.1f * acc[mt][nt][2];
            g_xn[(size_t)(r + 8) * DD + c + 1] = 0.1f * acc[mt][nt][3];
        }
}

// ---------------- gcn_out = relu(adj @ y + bias) via 3xTF32 MMA ----------------
__global__ __launch_bounds__(256) void k_gcn_mma(const float* __restrict__ bias) {
    int b = blockIdx.z;
    int i0 = blockIdx.y * 128, j0 = blockIdx.x * 64;
    const float* A = g_adj + (size_t)b * NSEQ * NSEQ;
    const float* Y = g_xn + (size_t)b * NSEQ * DD;
    __shared__ unsigned Ah[128][20], Al[128][20];
    __shared__ unsigned Bh[16][72], Bl[16][72];
    int t = threadIdx.x;
    int lane = t & 31, wid = t >> 5;
    int wm = wid >> 1, wn = wid & 1;
    int g = lane >> 2, tig = lane & 3;
    float acc[2][4][4];
    #pragma unroll
    for (int a = 0; a < 2; a++)
        #pragma unroll
        for (int n = 0; n < 4; n++)
            #pragma unroll
            for (int e = 0; e < 4; e++) acc[a][n][e] = 0.f;

    for (int kk = 0; kk < NSEQ; kk += 16) {
        #pragma unroll
        for (int q = 0; q < 2; q++) {
            int idx = t + q * 256;
            int row = idx >> 2, j = idx & 3;
            float4 xv = *(const float4*)(A + (size_t)(i0 + row) * NSEQ + kk + j * 4);
            uint4 h, l;
            h.x = f2tf(xv.x); l.x = f2tf(xv.x - __uint_as_float(h.x));
            h.y = f2tf(xv.y); l.y = f2tf(xv.y - __uint_as_float(h.y));
            h.z = f2tf(xv.z); l.z = f2tf(xv.z - __uint_as_float(h.z));
            h.w = f2tf(xv.w); l.w = f2tf(xv.w - __uint_as_float(h.w));
            *(uint4*)&Ah[row][j * 4] = h;
            *(uint4*)&Al[row][j * 4] = l;
        }
        {
            int k = t >> 4, n4 = t & 15;
            float4 yv = *(const float4*)(Y + (size_t)(kk + k) * DD + j0 + n4 * 4);
            uint4 h, l;
            h.x = f2tf(yv.x); l.x = f2tf(yv.x - __uint_as_float(h.x));
            h.y = f2tf(yv.y); l.y = f2tf(yv.y - __uint_as_float(h.y));
            h.z = f2tf(yv.z); l.z = f2tf(yv.z - __uint_as_float(h.z));
            h.w = f2tf(yv.w); l.w = f2tf(yv.w - __uint_as_float(h.w));
            *(uint4*)&Bh[k][n4 * 4] = h;
            *(uint4*)&Bl[k][n4 * 4] = l;
        }
        __syncthreads();
        #pragma unroll
        for (int ks = 0; ks < 2; ks++) {
            int k0 = ks * 8;
            unsigned ah[2][4], al[2][4], bh[4][2], bl[4][2];
            #pragma unroll
            for (int mt = 0; mt < 2; mt++) {
                int r = wm * 32 + mt * 16 + g;
                ah[mt][0] = Ah[r][k0 + tig];     ah[mt][1] = Ah[r + 8][k0 + tig];
                ah[mt][2] = Ah[r][k0 + tig + 4]; ah[mt][3] = Ah[r + 8][k0 + tig + 4];
                al[mt][0] = Al[r][k0 + tig];     al[mt][1] = Al[r + 8][k0 + tig];
                al[mt][2] = Al[r][k0 + tig + 4]; al[mt][3] = Al[r + 8][k0 + tig + 4];
            }
            #pragma unroll
            for (int nt = 0; nt < 4; nt++) {
                int n = wn * 32 + nt * 8 + g;
                bh[nt][0] = Bh[k0 + tig][n]; bh[nt][1] = Bh[k0 + tig + 4][n];
                bl[nt][0] = Bl[k0 + tig][n]; bl[nt][1] = Bl[k0 + tig + 4][n];
            }
            #pragma unroll
            for (int mt = 0; mt < 2; mt++)
                #pragma unroll
                for (int nt = 0; nt < 4; nt++) {
                    mma_tf32(acc[mt][nt], ah[mt], bh[nt]);
                    mma_tf32(acc[mt][nt], ah[mt], bl[nt]);
                    mma_tf32(acc[mt][nt], al[mt], bh[nt]);
                }
        }
        __syncthreads();
    }
    float* C = g_comb + (size_t)b * NSEQ * DD;
    #pragma unroll
    for (int mt = 0; mt < 2; mt++)
        #pragma unroll
        for (int nt = 0; nt < 4; nt++) {
            int r = i0 + wm * 32 + mt * 16 + g;
            int c = j0 + wn * 32 + nt * 8 + tig * 2;
            float b0 = bias[c], b1 = bias[c + 1];
            C[(size_t)r * DD + c]           = fmaxf(acc[mt][nt][0] + b0, 0.f);
            C[(size_t)r * DD + c + 1]       = fmaxf(acc[mt][nt][1] + b1, 0.f);
            C[(size_t)(r + 8) * DD + c]     = fmaxf(acc[mt][nt][2] + b0, 0.f);
            C[(size_t)(r + 8) * DD + c + 1] = fmaxf(acc[mt][nt][3] + b1, 0.f);
        }
}

// ---------------- fused conv1 -> BN -> ReLU -> conv2; combined += out ----------------
__global__ __launch_bounds__(256) void k_conv(const float* __restrict__ c1w, const float* __restrict__ c1b,
                                              const float* __restrict__ bng, const float* __restrict__ bnb,
                                              const float* __restrict__ c2w, const float* __restrict__ c2b) {
    __shared__ float xt[20][21];
    __shared__ float hs[32][18][18];
    __shared__ float w1[32][9], w2[32][9], sc[32], tc[32];
    int b = blockIdx.z;
    int oy0 = blockIdx.y * 16, ox0 = blockIdx.x * 16;
    int t = threadIdx.x;
    if (t < 32) {
        float s = bng[t] * rsqrtf(1.f + 1e-5f);
        sc[t] = s;
        tc[t] = c1b[t] * s + bnb[t];
    }
    for (int i = t; i < 288; i += 256) {
        w1[i / 9][i % 9] = c1w[i];
        w2[i / 9][i % 9] = c2w[i];
    }
    const float* xb = g_x + (size_t)b * NSEQ * DD;
    for (int i = t; i < 400; i += 256) {
        int ly = i / 20, lx = i % 20;
        int gy = oy0 - 2 + ly, gx = ox0 - 2 + lx;
        float v = 0.f;
        if (gy >= 0 && gy < NSEQ && gx >= 0 && gx < DD) v = xb[(size_t)gy * DD + gx];
        xt[ly][lx] = v;
    }
    __syncthreads();
    for (int i = t; i < 32 * 18 * 18; i += 256) {
        int c = i / 324, r = i % 324;
        int ly = r / 18, lx = r % 18;
        int gy = oy0 - 1 + ly, gx = ox0 - 1 + lx;
        float hv = 0.f;
        if (gy >= 0 && gy < NSEQ && gx >= 0 && gx < DD) {
            float a = 0.f;
            #pragma unroll
            for (int dy = 0; dy < 3; dy++)
                #pragma unroll
                for (int dx = 0; dx < 3; dx++)
                    a += xt[ly + dy][lx + dx] * w1[c][dy * 3 + dx];
            hv = fmaxf(a * sc[c] + tc[c], 0.f);
        }
        hs[c][ly][lx] = hv;
    }
    __syncthreads();
    int oy = t >> 4, ox = t & 15;
    float acc = c2b[0];
    #pragma unroll 4
    for (int c = 0; c < 32; c++) {
        #pragma unroll
        for (int dy = 0; dy < 3; dy++)
            #pragma unroll
            for (int dx = 0; dx < 3; dx++)
                acc += hs[c][oy + dy][ox + dx] * w2[c][dy * 3 + dx];
    }
    g_comb[(size_t)b * NSEQ * DD + (size_t)(oy0 + oy) * DD + ox0 + ox] += acc;
}

// ---------------- gate + residual mix ----------------
__global__ void k_gate(const float* __restrict__ gw, const float* __restrict__ gb) {
    int row = blockIdx.x;
    int t = threadIdx.x;
    size_t off = (size_t)row * DD;
    float x1 = g_x[off + t],    x2 = g_x[off + t + 256];
    float c1 = g_comb[off + t], c2 = g_comb[off + t + 256];
    float p = x1 * gw[t] + x2 * gw[t + 256] + c1 * gw[512 + t] + c2 * gw[768 + t];
    #pragma unroll
    for (int o = 16; o > 0; o >>= 1) p += __shfl_xor_sync(0xffffffffu, p, o);
    __shared__ float ws[8];
    if ((t & 31) == 0) ws[t >> 5] = p;
    __syncthreads();
    float tot = ws[0] + ws[1] + ws[2] + ws[3] + ws[4] + ws[5] + ws[6] + ws[7];
    float g = 1.f / (1.f + expf(-(tot + gb[0])));
    g_x[off + t]       = g * x1 + (1.f - g) * c1;
    g_x[off + t + 256] = g * x2 + (1.f - g) * c2;
}

// ---------------- mean pool + classifier ----------------
__global__ void k_cls(const float* __restrict__ w1, const float* __restrict__ b1,
                      const float* __restrict__ w2, const float* __restrict__ b2,
                      float* __restrict__ out) {
    int b = blockIdx.x;
    int t = threadIdx.x;
    __shared__ float pooled[512], h1[512];
    float s = 0.f;
    const float* xb = g_x + (size_t)b * NSEQ * DD;
    for (int n = 0; n < NSEQ; n++) s += xb[(size_t)n * DD + t];
    pooled[t] = s * (1.f / NSEQ);
    __syncthreads();
    float a = b1[t];
    for (int d = 0; d < 512; d++) a += pooled[d] * w1[d * 512 + t];
    h1[t] = fmaxf(a, 0.f);
    __syncthreads();
    if (t < LABELS_) {
        float a2 = b2[t];
        for (int d = 0; d < 512; d++) a2 += h1[d] * w2[d * LABELS_ + t];
        out[b * LABELS_ + t] = a2;
    }
}

// ---------------- launch ----------------
extern "C" void kernel_launch(void* const* d_in, const int* in_sizes, int n_in,
                              void* d_out, int out_size) {
    const int*   ids   = (const int*)  d_in[0];
    const float* e1    = (const float*)d_in[1];
    const float* e2    = (const float*)d_in[2];
    const float* emb   = (const float*)d_in[3];
    const float* ep_w  = (const float*)d_in[4];
    const float* ep_b  = (const float*)d_in[5];
    const float* gcn_w = (const float*)d_in[6];
    const float* gcn_b = (const float*)d_in[7];
    const float* c1w   = (const float*)d_in[8];
    const float* c1b   = (const float*)d_in[9];
    const float* bng   = (const float*)d_in[10];
    const float* bnb   = (const float*)d_in[11];
    const float* c2w   = (const float*)d_in[12];
    const float* c2b   = (const float*)d_in[13];
    const float* gw    = (const float*)d_in[14];
    const float* gb    = (const float*)d_in[15];
    const float* clw1  = (const float*)d_in[16];
    const float* clb1  = (const float*)d_in[17];
    const float* clw2  = (const float*)d_in[18];
    const float* clb2  = (const float*)d_in[19];
    float* out = (float*)d_out;

    k_embed<<<BB * NSEQ, 64>>>(ids, emb);
    k_entpool<<<BB, 256>>>(e1, e2);
    k_entproj<<<BB, 256>>>(ep_w, ep_b);

    for (int i = 0; i < 2; i++) {
        k_rownorm<<<BB * NSEQ, 128>>>();
        k_sim_mma<<<dim3(4, 2, BB), 256>>>();
        k_topk<<<BB * NSEQ / 128, 128>>>();
        k_zero_adj<<<(BB * NSEQ * NSEQ / 4 + 255) / 256, 256>>>();
        k_adjbuild<<<(BB * NSEQ * KTOP + 255) / 256, 256>>>();
        k_xqw_mma<<<dim3(8, 256), 256>>>(gcn_w + (size_t)i * DD * DD);
        k_gcn_mma<<<dim3(8, 2, BB), 256>>>(gcn_b + i * DD);
        k_conv<<<dim3(32, 16, BB), 256>>>(c1w + i * 288, c1b + i * 32,
                                          bng + i * 32, bnb + i * 32,
                                          c2w + i * 288, c2b + i);
        k_gate<<<BB * NSEQ, 256>>>(gw, gb);
    }
    k_cls<<<BB, 512>>>(clw1, clb1, clw2, clb2, out);
}

// round 4
// speedup vs baseline: 2.4681x; 2.2533x over previous
#include <cuda_runtime.h>
#include <math.h>

#define BB    128
#define NSEQ  256
#define DD    512          // NODE
#define DEMB_ 256
#define KTOP  8
#define LABELS_ 19

// ---------------- scratch (device globals; no allocations) ----------------
__device__ float g_x[BB * NSEQ * DD];        // node features [B,N,512]
__device__ float g_xn[BB * NSEQ * DD];       // y = x@qw
__device__ float g_adj[BB * NSEQ * NSEQ];    // sim, then adj
__device__ float g_comb[BB * NSEQ * DD];     // gcn_out + conv_out
__device__ float g_entcat[BB * 2 * DEMB_];
__device__ float g_rnorm[BB * NSEQ];
__device__ float g_vals[BB * NSEQ * KTOP];
__device__ int   g_idx[BB * NSEQ * KTOP];

// ---------------- tf32 helpers ----------------
__device__ __forceinline__ unsigned f2tf(float f) {
    unsigned u;
    asm("cvt.rna.tf32.f32 %0, %1;" : "=r"(u) : "f"(f));
    return u;
}
__device__ __forceinline__ void mma_tf32(float* d, const unsigned* a, const unsigned* b) {
    asm volatile(
        "mma.sync.aligned.m16n8k8.row.col.f32.tf32.tf32.f32 "
        "{%0,%1,%2,%3}, {%4,%5,%6,%7}, {%8,%9}, {%0,%1,%2,%3};"
        : "+f"(d[0]), "+f"(d[1]), "+f"(d[2]), "+f"(d[3])
        : "r"(a[0]), "r"(a[1]), "r"(a[2]), "r"(a[3]), "r"(b[0]), "r"(b[1]));
}

// ---------------- embedding gather ----------------
__global__ void k_embed(const int* __restrict__ ids, const float* __restrict__ emb) {
    int row = blockIdx.x;
    int id = ids[row];
    const float4* src = (const float4*)(emb + (size_t)id * DEMB_);
    float4* dst = (float4*)(g_x + (size_t)row * DD);
    dst[threadIdx.x] = src[threadIdx.x];
}

// ---------------- entity masked-mean pooling ----------------
__global__ void k_entpool(const float* __restrict__ e1, const float* __restrict__ e2) {
    int b = blockIdx.x;
    int t = threadIdx.x;
    __shared__ float m1[NSEQ], m2[NSEQ];
    __shared__ float c1s, c2s;
    m1[t] = e1[b * NSEQ + t];
    m2[t] = e2[b * NSEQ + t];
    __syncthreads();
    if (t == 0) {
        float a = 0.f, c = 0.f;
        for (int n = 0; n < NSEQ; n++) { a += m1[n]; c += m2[n]; }
        c1s = a; c2s = c;
    }
    __syncthreads();
    float s1 = 0.f, s2 = 0.f;
    const float* xb = g_x + (size_t)b * NSEQ * DD;
    for (int n = 0; n < NSEQ; n++) {
        float v = xb[(size_t)n * DD + t];
        s1 += v * m1[n];
        s2 += v * m2[n];
    }
    g_entcat[b * 512 + t]       = s1 / (c1s + 1e-13f);
    g_entcat[b * 512 + 256 + t] = s2 / (c2s + 1e-13f);
}

// ---------------- ent = entcat @ ep_w + ep_b, broadcast (coalesced stores) ----------------
__global__ void k_entproj(const float* __restrict__ ep_w, const float* __restrict__ ep_b) {
    int b = blockIdx.x;
    int j = threadIdx.x;
    __shared__ float ec[512];
    __shared__ float accs[256];
    ec[j]       = g_entcat[b * 512 + j];
    ec[j + 256] = g_entcat[b * 512 + j + 256];
    __syncthreads();
    float acc = ep_b[j];
    for (int d = 0; d < 512; d++) acc += ec[d] * ep_w[d * DEMB_ + j];
    accs[j] = acc;
    __syncthreads();
    float* xb = g_x + (size_t)b * NSEQ * DD;
    for (int i = j; i < NSEQ * 256; i += 256) {
        int n = i >> 8, c = i & 255;
        xb[(size_t)n * DD + DEMB_ + c] = accs[c];
    }
}

// ---------------- per-row inverse L2 norm (one warp per row) ----------------
__global__ void k_norms() {
    int row = blockIdx.x * 8 + (threadIdx.x >> 5);
    int lane = threadIdx.x & 31;
    const float4* xr = (const float4*)(g_x + (size_t)row * DD);
    float ss = 0.f;
    #pragma unroll
    for (int q = 0; q < 4; q++) {
        float4 v = xr[lane + q * 32];
        ss += v.x * v.x + v.y * v.y + v.z * v.z + v.w * v.w;
    }
    #pragma unroll
    for (int o = 16; o > 0; o >>= 1) ss += __shfl_xor_sync(0xffffffffu, ss, o);
    if (lane == 0) g_rnorm[row] = 1.f / fmaxf(sqrtf(ss), 1e-12f);
}

// ---------------- sim = (x @ x^T) * rn_i * rn_j via split TF32 MMA ----------------
__global__ __launch_bounds__(256) void k_sim_mma() {
    int b = blockIdx.z;
    int i0 = blockIdx.y * 128, j0 = blockIdx.x * 64;
    const float* A = g_x + (size_t)b * NSEQ * DD;
    __shared__ unsigned Ah[128][20], Al[128][20];
    __shared__ unsigned Bh[16][72], Bl[16][72];
    __shared__ float rnI[128], rnJ[64];
    int t = threadIdx.x;
    int lane = t & 31, wid = t >> 5;
    int wm = wid >> 1, wn = wid & 1;
    int g = lane >> 2, tig = lane & 3;
    if (t < 128) rnI[t] = g_rnorm[b * NSEQ + i0 + t];
    else if (t < 192) rnJ[t - 128] = g_rnorm[b * NSEQ + j0 + t - 128];
    float acc[2][4][4];
    #pragma unroll
    for (int a = 0; a < 2; a++)
        #pragma unroll
        for (int n = 0; n < 4; n++)
            #pragma unroll
            for (int e = 0; e < 4; e++) acc[a][n][e] = 0.f;

    for (int kk = 0; kk < DD; kk += 16) {
        #pragma unroll
        for (int q = 0; q < 2; q++) {
            int idx = t + q * 256;
            int row = idx >> 2, j = idx & 3;
            float4 xv = *(const float4*)(A + (size_t)(i0 + row) * DD + kk + j * 4);
            uint4 h, l;
            h.x = f2tf(xv.x); l.x = f2tf(xv.x - __uint_as_float(h.x));
            h.y = f2tf(xv.y); l.y = f2tf(xv.y - __uint_as_float(h.y));
            h.z = f2tf(xv.z); l.z = f2tf(xv.z - __uint_as_float(h.z));
            h.w = f2tf(xv.w); l.w = f2tf(xv.w - __uint_as_float(h.w));
            *(uint4*)&Ah[row][j * 4] = h;
            *(uint4*)&Al[row][j * 4] = l;
        }
        {
            int n = t >> 2, j = t & 3;
            float4 xv = *(const float4*)(A + (size_t)(j0 + n) * DD + kk + j * 4);
            float f[4] = {xv.x, xv.y, xv.z, xv.w};
            #pragma unroll
            for (int e = 0; e < 4; e++) {
                unsigned h = f2tf(f[e]);
                Bh[j * 4 + e][n] = h;
                Bl[j * 4 + e][n] = f2tf(f[e] - __uint_as_float(h));
            }
        }
        __syncthreads();
        #pragma unroll
        for (int ks = 0; ks < 2; ks++) {
            int k0 = ks * 8;
            unsigned ah[2][4], al[2][4], bh[4][2], bl[4][2];
            #pragma unroll
            for (int mt = 0; mt < 2; mt++) {
                int r = wm * 32 + mt * 16 + g;
                ah[mt][0] = Ah[r][k0 + tig];     ah[mt][1] = Ah[r + 8][k0 + tig];
                ah[mt][2] = Ah[r][k0 + tig + 4]; ah[mt][3] = Ah[r + 8][k0 + tig + 4];
                al[mt][0] = Al[r][k0 + tig];     al[mt][1] = Al[r + 8][k0 + tig];
                al[mt][2] = Al[r][k0 + tig + 4]; al[mt][3] = Al[r + 8][k0 + tig + 4];
            }
            #pragma unroll
            for (int nt = 0; nt < 4; nt++) {
                int n = wn * 32 + nt * 8 + g;
                bh[nt][0] = Bh[k0 + tig][n]; bh[nt][1] = Bh[k0 + tig + 4][n];
                bl[nt][0] = Bl[k0 + tig][n]; bl[nt][1] = Bl[k0 + tig + 4][n];
            }
            #pragma unroll
            for (int mt = 0; mt < 2; mt++)
                #pragma unroll
                for (int nt = 0; nt < 4; nt++) {
                    mma_tf32(acc[mt][nt], ah[mt], bh[nt]);
                    mma_tf32(acc[mt][nt], ah[mt], bl[nt]);
                    mma_tf32(acc[mt][nt], al[mt], bh[nt]);
                }
        }
        __syncthreads();
    }
    float* C = g_adj + (size_t)b * NSEQ * NSEQ;
    #pragma unroll
    for (int mt = 0; mt < 2; mt++)
        #pragma unroll
        for (int nt = 0; nt < 4; nt++) {
            int rl = wm * 32 + mt * 16 + g;
            int cl = wn * 32 + nt * 8 + tig * 2;
            int r = i0 + rl, c = j0 + cl;
            float s0 = rnI[rl] * rnJ[cl], s1 = rnI[rl] * rnJ[cl + 1];
            float s2 = rnI[rl + 8] * rnJ[cl], s3 = rnI[rl + 8] * rnJ[cl + 1];
            C[(size_t)r * NSEQ + c]           = acc[mt][nt][0] * s0;
            C[(size_t)r * NSEQ + c + 1]       = acc[mt][nt][1] * s1;
            C[(size_t)(r + 8) * NSEQ + c]     = acc[mt][nt][2] * s2;
            C[(size_t)(r + 8) * NSEQ + c + 1] = acc[mt][nt][3] * s3;
        }
}

// ---------------- top-8 with coalesced smem staging ----------------
__global__ __launch_bounds__(128) void k_topk() {
    __shared__ float sh[128][36];
    int rb = blockIdx.x * 128;
    int t = threadIdx.x;
    float v[KTOP]; int id[KTOP];
    #pragma unroll
    for (int k = 0; k < KTOP; k++) { v[k] = -1e30f; id[k] = -1; }
    for (int ch = 0; ch < 8; ch++) {
        __syncthreads();
        for (int q = t; q < 1024; q += 128) {
            int row = q >> 3, c4 = q & 7;
            float4 x = *(const float4*)(g_adj + (size_t)(rb + row) * NSEQ + ch * 32 + c4 * 4);
            *(float4*)&sh[row][c4 * 4] = x;
        }
        __syncthreads();
        #pragma unroll 4
        for (int c = 0; c < 32; c++) {
            float x = sh[t][c];
            if (x > v[KTOP - 1]) {
                int m = ch * 32 + c;
                int p = KTOP - 1;
                while (p > 0 && v[p - 1] < x) { v[p] = v[p - 1]; id[p] = id[p - 1]; p--; }
                v[p] = x; id[p] = m;
            }
        }
    }
    int row = rb + t;
    #pragma unroll
    for (int k = 0; k < KTOP; k++) {
        g_vals[row * KTOP + k] = v[k];
        g_idx[row * KTOP + k]  = id[k];
    }
}

// ---------------- zero adj ----------------
__global__ void k_zero_adj() {
    int i = blockIdx.x * blockDim.x + threadIdx.x;
    int n4 = BB * NSEQ * NSEQ / 4;
    if (i < n4) ((float4*)g_adj)[i] = make_float4(0.f, 0.f, 0.f, 0.f);
}

// ---------------- adj = (mask + mask^T)/2 via atomic scatter ----------------
__global__ void k_adjbuild() {
    int t = blockIdx.x * blockDim.x + threadIdx.x;
    if (t >= BB * NSEQ * KTOP) return;
    int row = t / KTOP;
    int b = row / NSEQ, n = row % NSEQ;
    float v = 0.5f * g_vals[t];
    int m = g_idx[t];
    float* adjb = g_adj + (size_t)b * NSEQ * NSEQ;
    atomicAdd(&adjb[n * NSEQ + m], v);
    atomicAdd(&adjb[m * NSEQ + n], v);
}

// ---------------- xqw = x @ sign(W) * 0.1 via 2xTF32 MMA ----------------
__global__ __launch_bounds__(256) void k_xqw_mma(const float* __restrict__ W) {
    int i0 = blockIdx.y * 128, j0 = blockIdx.x * 64;
    __shared__ unsigned Ah[128][20], Al[128][20];
    __shared__ unsigned Bs[16][72];
    int t = threadIdx.x;
    int lane = t & 31, wid = t >> 5;
    int wm = wid >> 1, wn = wid & 1;
    int g = lane >> 2, tig = lane & 3;
    float acc[2][4][4];
    #pragma unroll
    for (int a = 0; a < 2; a++)
        #pragma unroll
        for (int n = 0; n < 4; n++)
            #pragma unroll
            for (int e = 0; e < 4; e++) acc[a][n][e] = 0.f;

    for (int kk = 0; kk < DD; kk += 16) {
        #pragma unroll
        for (int q = 0; q < 2; q++) {
            int idx = t + q * 256;
            int row = idx >> 2, j = idx & 3;
            float4 xv = *(const float4*)(g_x + (size_t)(i0 + row) * DD + kk + j * 4);
            uint4 h, l;
            h.x = f2tf(xv.x); l.x = f2tf(xv.x - __uint_as_float(h.x));
            h.y = f2tf(xv.y); l.y = f2tf(xv.y - __uint_as_float(h.y));
            h.z = f2tf(xv.z); l.z = f2tf(xv.z - __uint_as_float(h.z));
            h.w = f2tf(xv.w); l.w = f2tf(xv.w - __uint_as_float(h.w));
            *(uint4*)&Ah[row][j * 4] = h;
            *(uint4*)&Al[row][j * 4] = l;
        }
        {
            int k = t >> 4, n4 = t & 15;
            float4 w = *(const float4*)(W + (size_t)(kk + k) * DD + j0 + n4 * 4);
            uint4 q;
            q.x = __float_as_uint((w.x > 0.1f) ? 1.f : ((w.x < -0.1f) ? -1.f : 0.f));
            q.y = __float_as_uint((w.y > 0.1f) ? 1.f : ((w.y < -0.1f) ? -1.f : 0.f));
            q.z = __float_as_uint((w.z > 0.1f) ? 1.f : ((w.z < -0.1f) ? -1.f : 0.f));
            q.w = __float_as_uint((w.w > 0.1f) ? 1.f : ((w.w < -0.1f) ? -1.f : 0.f));
            *(uint4*)&Bs[k][n4 * 4] = q;
        }
        __syncthreads();
        #pragma unroll
        for (int ks = 0; ks < 2; ks++) {
            int k0 = ks * 8;
            unsigned ah[2][4], al[2][4], bs[4][2];
            #pragma unroll
            for (int mt = 0; mt < 2; mt++) {
                int r = wm * 32 + mt * 16 + g;
                ah[mt][0] = Ah[r][k0 + tig];     ah[mt][1] = Ah[r + 8][k0 + tig];
                ah[mt][2] = Ah[r][k0 + tig + 4]; ah[mt][3] = Ah[r + 8][k0 + tig + 4];
                al[mt][0] = Al[r][k0 + tig];     al[mt][1] = Al[r + 8][k0 + tig];
                al[mt][2] = Al[r][k0 + tig + 4]; al[mt][3] = Al[r + 8][k0 + tig + 4];
            }
            #pragma unroll
            for (int nt = 0; nt < 4; nt++) {
                int n = wn * 32 + nt * 8 + g;
                bs[nt][0] = Bs[k0 + tig][n]; bs[nt][1] = Bs[k0 + tig + 4][n];
            }
            #pragma unroll
            for (int mt = 0; mt < 2; mt++)
                #pragma unroll
                for (int nt = 0; nt < 4; nt++) {
                    mma_tf32(acc[mt][nt], ah[mt], bs[nt]);
                    mma_tf32(acc[mt][nt], al[mt], bs[nt]);
                }
        }
        __syncthreads();
    }
    #pragma unroll
    for (int mt = 0; mt < 2; mt++)
        #pragma unroll
        for (int nt = 0; nt < 4; nt++) {
            int r = i0 + wm * 32 + mt * 16 + g;
            int c = j0 + wn * 32 + nt * 8 + tig * 2;
            g_xn[(size_t)r * DD + c]           = 0.1f * acc[mt][nt][0];
            g_xn[(size_t)r * DD + c + 1]       = 0.1f * acc[mt][nt][1];
            g_xn[(size_t)(r + 8) * DD + c]     = 0.1f * acc[mt][nt][2];
            g_xn[(size_t)(r + 8) * DD + c + 1] = 0.1f * acc[mt][nt][3];
        }
}

// ---------------- gcn_out = relu(adj @ y + bias) via split TF32 MMA ----------------
__global__ __launch_bounds__(256) void k_gcn_mma(const float* __restrict__ bias) {
    int b = blockIdx.z;
    int i0 = blockIdx.y * 128, j0 = blockIdx.x * 64;
    const float* A = g_adj + (size_t)b * NSEQ * NSEQ;
    const float* Y = g_xn + (size_t)b * NSEQ * DD;
    __shared__ unsigned Ah[128][20], Al[128][20];
    __shared__ unsigned Bh[16][72], Bl[16][72];
    int t = threadIdx.x;
    int lane = t & 31, wid = t >> 5;
    int wm = wid >> 1, wn = wid & 1;
    int g = lane >> 2, tig = lane & 3;
    float acc[2][4][4];
    #pragma unroll
    for (int a = 0; a < 2; a++)
        #pragma unroll
        for (int n = 0; n < 4; n++)
            #pragma unroll
            for (int e = 0; e < 4; e++) acc[a][n][e] = 0.f;

    for (int kk = 0; kk < NSEQ; kk += 16) {
        #pragma unroll
        for (int q = 0; q < 2; q++) {
            int idx = t + q * 256;
            int row = idx >> 2, j = idx & 3;
            float4 xv = *(const float4*)(A + (size_t)(i0 + row) * NSEQ + kk + j * 4);
            uint4 h, l;
            h.x = f2tf(xv.x); l.x = f2tf(xv.x - __uint_as_float(h.x));
            h.y = f2tf(xv.y); l.y = f2tf(xv.y - __uint_as_float(h.y));
            h.z = f2tf(xv.z); l.z = f2tf(xv.z - __uint_as_float(h.z));
            h.w = f2tf(xv.w); l.w = f2tf(xv.w - __uint_as_float(h.w));
            *(uint4*)&Ah[row][j * 4] = h;
            *(uint4*)&Al[row][j * 4] = l;
        }
        {
            int k = t >> 4, n4 = t & 15;
            float4 yv = *(const float4*)(Y + (size_t)(kk + k) * DD + j0 + n4 * 4);
            uint4 h, l;
            h.x = f2tf(yv.x); l.x = f2tf(yv.x - __uint_as_float(h.x));
            h.y = f2tf(yv.y); l.y = f2tf(yv.y - __uint_as_float(h.y));
            h.z = f2tf(yv.z); l.z = f2tf(yv.z - __uint_as_float(h.z));
            h.w = f2tf(yv.w); l.w = f2tf(yv.w - __uint_as_float(h.w));
            *(uint4*)&Bh[k][n4 * 4] = h;
            *(uint4*)&Bl[k][n4 * 4] = l;
        }
        __syncthreads();
        #pragma unroll
        for (int ks = 0; ks < 2; ks++) {
            int k0 = ks * 8;
            unsigned ah[2][4], al[2][4], bh[4][2], bl[4][2];
            #pragma unroll
            for (int mt = 0; mt < 2; mt++) {
                int r = wm * 32 + mt * 16 + g;
                ah[mt][0] = Ah[r][k0 + tig];     ah[mt][1] = Ah[r + 8][k0 + tig];
                ah[mt][2] = Ah[r][k0 + tig + 4]; ah[mt][3] = Ah[r + 8][k0 + tig + 4];
                al[mt][0] = Al[r][k0 + tig];     al[mt][1] = Al[r + 8][k0 + tig];
                al[mt][2] = Al[r][k0 + tig + 4]; al[mt][3] = Al[r + 8][k0 + tig + 4];
            }
            #pragma unroll
            for (int nt = 0; nt < 4; nt++) {
                int n = wn * 32 + nt * 8 + g;
                bh[nt][0] = Bh[k0 + tig][n]; bh[nt][1] = Bh[k0 + tig + 4][n];
                bl[nt][0] = Bl[k0 + tig][n]; bl[nt][1] = Bl[k0 + tig + 4][n];
            }
            #pragma unroll
            for (int mt = 0; mt < 2; mt++)
                #pragma unroll
                for (int nt = 0; nt < 4; nt++) {
                    mma_tf32(acc[mt][nt], ah[mt], bh[nt]);
                    mma_tf32(acc[mt][nt], ah[mt], bl[nt]);
                    mma_tf32(acc[mt][nt], al[mt], bh[nt]);
                }
        }
        __syncthreads();
    }
    float* C = g_comb + (size_t)b * NSEQ * DD;
    #pragma unroll
    for (int mt = 0; mt < 2; mt++)
        #pragma unroll
        for (int nt = 0; nt < 4; nt++) {
            int r = i0 + wm * 32 + mt * 16 + g;
            int c = j0 + wn * 32 + nt * 8 + tig * 2;
            float b0 = bias[c], b1 = bias[c + 1];
            C[(size_t)r * DD + c]           = fmaxf(acc[mt][nt][0] + b0, 0.f);
            C[(size_t)r * DD + c + 1]       = fmaxf(acc[mt][nt][1] + b1, 0.f);
            C[(size_t)(r + 8) * DD + c]     = fmaxf(acc[mt][nt][2] + b0, 0.f);
            C[(size_t)(r + 8) * DD + c + 1] = fmaxf(acc[mt][nt][3] + b1, 0.f);
        }
}

// ---------------- fused conv: 32x64 tile, 2-channel chunks, 4x2 register blocking ----------------
__global__ __launch_bounds__(256) void k_conv(const float* __restrict__ c1w, const float* __restrict__ c1b,
                                              const float* __restrict__ bng, const float* __restrict__ bnb,
                                              const float* __restrict__ c2w, const float* __restrict__ c2b) {
    __shared__ float xt[36][69];
    __shared__ float hs[2][36][69];
    __shared__ float w1s[32][9], w2s[32][9], scs[32], tcs[32];
    int b = blockIdx.z;
    int oy0 = blockIdx.y * 32, ox0 = blockIdx.x * 64;
    int t = threadIdx.x;
    if (t < 32) {
        float s = bng[t] * rsqrtf(1.f + 1e-5f);
        scs[t] = s;
        tcs[t] = c1b[t] * s + bnb[t];
    }
    for (int i = t; i < 288; i += 256) {
        w1s[i / 9][i % 9] = c1w[i];
        w2s[i / 9][i % 9] = c2w[i];
    }
    const float* xb = g_x + (size_t)b * NSEQ * DD;
    for (int i = t; i < 36 * 68; i += 256) {
        int r = i / 68, c = i % 68;
        int gy = oy0 - 2 + r, gx = ox0 - 2 + c;
        xt[r][c] = (gy >= 0 && gy < NSEQ && gx >= 0 && gx < DD) ? xb[(size_t)gy * DD + gx] : 0.f;
    }
    __syncthreads();

    // conv2 output mapping: 4 rows x 2 cols per thread
    int rg = t & 7, cp = t >> 3;                 // rg: row group (8), cp: col pair (32)
    int oy = rg * 4, ox = cp * 2;
    float acc[4][2] = {};

    for (int chunk = 0; chunk < 16; chunk++) {
        // ---- stage h for 2 channels (need h rows 0..35, cols 0..65) ----
        for (int tau = t; tau < 2 * 9 * 33; tau += 256) {
            int g2 = tau % 9;
            int cloc = (tau / 9) & 1;
            int q = tau / 18;
            int cg = chunk * 2 + cloc;
            int ly0 = g2 * 4, lx0 = q * 2;
            float w[9];
            #pragma unroll
            for (int u = 0; u < 9; u++) w[u] = w1s[cg][u];
            float sc = scs[cg], tc = tcs[cg];
            float hb[6][4];
            #pragma unroll
            for (int yy = 0; yy < 6; yy++) {
                int xr = ly0 + yy;
                bool ok = xr < 36;
                #pragma unroll
                for (int xx = 0; xx < 4; xx++)
                    hb[yy][xx] = ok ? xt[xr][lx0 + xx] : 0.f;
            }
            #pragma unroll
            for (int yy = 0; yy < 4; yy++) {
                int ly = ly0 + yy;
                int gy = oy0 - 1 + ly;
                #pragma unroll
                for (int xx = 0; xx < 2; xx++) {
                    int gx = ox0 - 1 + lx0 + xx;
                    float a = 0.f;
                    #pragma unroll
                    for (int dy = 0; dy < 3; dy++)
                        #pragma unroll
                        for (int dx = 0; dx < 3; dx++)
                            a += hb[yy + dy][xx + dx] * w[dy * 3 + dx];
                    float hv = (gy >= 0 && gy < NSEQ && gx >= 0 && gx < DD)
                                   ? fmaxf(a * sc + tc, 0.f) : 0.f;
                    hs[cloc][ly][lx0 + xx] = hv;
                }
            }
        }
        __syncthreads();
        // ---- conv2 accumulate over these 2 channels ----
        #pragma unroll
        for (int cloc = 0; cloc < 2; cloc++) {
            int cg = chunk * 2 + cloc;
            float w[9];
            #pragma unroll
            for (int u = 0; u < 9; u++) w[u] = w2s[cg][u];
            float hb[6][4];
            #pragma unroll
            for (int yy = 0; yy < 6; yy++)
                #pragma unroll
                for (int xx = 0; xx < 4; xx++)
                    hb[yy][xx] = hs[cloc][oy + yy][ox + xx];
            #pragma unroll
            for (int yy = 0; yy < 4; yy++)
                #pragma unroll
                for (int xx = 0; xx < 2; xx++)
                    #pragma unroll
                    for (int dy = 0; dy < 3; dy++)
                        #pragma unroll
                        for (int dx = 0; dx < 3; dx++)
                            acc[yy][xx] += hb[yy + dy][xx + dx] * w[dy * 3 + dx];
        }
        __syncthreads();
    }
    // stage outputs in smem for coalesced global accumulate
    float bias = c2b[0];
    #pragma unroll
    for (int yy = 0; yy < 4; yy++)
        #pragma unroll
        for (int xx = 0; xx < 2; xx++)
            hs[0][oy + yy][ox + xx] = acc[yy][xx] + bias;
    __syncthreads();
    float* cb = g_comb + (size_t)b * NSEQ * DD;
    for (int i = t; i < 32 * 64; i += 256) {
        int r = i >> 6, c = i & 63;
        cb[(size_t)(oy0 + r) * DD + ox0 + c] += hs[0][r][c];
    }
}

// ---------------- gate + residual mix ----------------
__global__ void k_gate(const float* __restrict__ gw, const float* __restrict__ gb) {
    int row = blockIdx.x;
    int t = threadIdx.x;
    size_t off = (size_t)row * DD;
    float x1 = g_x[off + t],    x2 = g_x[off + t + 256];
    float c1 = g_comb[off + t], c2 = g_comb[off + t + 256];
    float p = x1 * gw[t] + x2 * gw[t + 256] + c1 * gw[512 + t] + c2 * gw[768 + t];
    #pragma unroll
    for (int o = 16; o > 0; o >>= 1) p += __shfl_xor_sync(0xffffffffu, p, o);
    __shared__ float ws[8];
    if ((t & 31) == 0) ws[t >> 5] = p;
    __syncthreads();
    float tot = ws[0] + ws[1] + ws[2] + ws[3] + ws[4] + ws[5] + ws[6] + ws[7];
    float g = 1.f / (1.f + expf(-(tot + gb[0])));
    g_x[off + t]       = g * x1 + (1.f - g) * c1;
    g_x[off + t + 256] = g * x2 + (1.f - g) * c2;
}

// ---------------- mean pool + classifier ----------------
__global__ void k_cls(const float* __restrict__ w1, const float* __restrict__ b1,
                      const float* __restrict__ w2, const float* __restrict__ b2,
                      float* __restrict__ out) {
    int b = blockIdx.x;
    int t = threadIdx.x;
    __shared__ float pooled[512], h1[512];
    float s = 0.f;
    const float* xb = g_x + (size_t)b * NSEQ * DD;
    for (int n = 0; n < NSEQ; n++) s += xb[(size_t)n * DD + t];
    pooled[t] = s * (1.f / NSEQ);
    __syncthreads();
    float a = b1[t];
    for (int d = 0; d < 512; d++) a += pooled[d] * w1[d * 512 + t];
    h1[t] = fmaxf(a, 0.f);
    __syncthreads();
    if (t < LABELS_) {
        float a2 = b2[t];
        for (int d = 0; d < 512; d++) a2 += h1[d] * w2[d * LABELS_ + t];
        out[b * LABELS_ + t] = a2;
    }
}

// ---------------- launch ----------------
extern "C" void kernel_launch(void* const* d_in, const int* in_sizes, int n_in,
                              void* d_out, int out_size) {
    const int*   ids   = (const int*)  d_in[0];
    const float* e1    = (const float*)d_in[1];
    const float* e2    = (const float*)d_in[2];
    const float* emb   = (const float*)d_in[3];
    const float* ep_w  = (const float*)d_in[4];
    const float* ep_b  = (const float*)d_in[5];
    const float* gcn_w = (const float*)d_in[6];
    const float* gcn_b = (const float*)d_in[7];
    const float* c1w   = (const float*)d_in[8];
    const float* c1b   = (const float*)d_in[9];
    const float* bng   = (const float*)d_in[10];
    const float* bnb   = (const float*)d_in[11];
    const float* c2w   = (const float*)d_in[12];
    const float* c2b   = (const float*)d_in[13];
    const float* gw    = (const float*)d_in[14];
    const float* gb    = (const float*)d_in[15];
    const float* clw1  = (const float*)d_in[16];
    const float* clb1  = (const float*)d_in[17];
    const float* clw2  = (const float*)d_in[18];
    const float* clb2  = (const float*)d_in[19];
    float* out = (float*)d_out;

    k_embed<<<BB * NSEQ, 64>>>(ids, emb);
    k_entpool<<<BB, 256>>>(e1, e2);
    k_entproj<<<BB, 256>>>(ep_w, ep_b);

    for (int i = 0; i < 2; i++) {
        k_norms<<<BB * NSEQ / 8, 256>>>();
        k_sim_mma<<<dim3(4, 2, BB), 256>>>();
        k_topk<<<BB * NSEQ / 128, 128>>>();
        k_zero_adj<<<(BB * NSEQ * NSEQ / 4 + 255) / 256, 256>>>();
        k_adjbuild<<<(BB * NSEQ * KTOP + 255) / 256, 256>>>();
        k_xqw_mma<<<dim3(8, 256), 256>>>(gcn_w + (size_t)i * DD * DD);
        k_gcn_mma<<<dim3(8, 2, BB), 256>>>(gcn_b + i * DD);
        k_conv<<<dim3(8, 8, BB), 256>>>(c1w + i * 288, c1b + i * 32,
                                        bng + i * 32, bnb + i * 32,
                                        c2w + i * 288, c2b + i);
        k_gate<<<BB * NSEQ, 256>>>(gw, gb);
    }
    k_cls<<<BB, 512>>>(clw1, clb1, clw2, clb2, out);
}

// round 5
// speedup vs baseline: 2.8086x; 1.1380x over previous
#include <cuda_runtime.h>
#include <cuda_bf16.h>
#include <math.h>

#define BB    128
#define NSEQ  256
#define DD    512          // NODE
#define DEMB_ 256
#define KTOP  8
#define LABELS_ 19

// ---------------- scratch (device globals; no allocations) ----------------
__device__ float g_x[BB * NSEQ * DD];        // node features [B,N,512]
__device__ float g_xn[BB * NSEQ * DD];       // y = x@qw
__device__ float g_adj[BB * NSEQ * NSEQ];    // sim, then adj
__device__ float g_comb[BB * NSEQ * DD];     // gcn_out + conv_out
__device__ float g_entcat[BB * 2 * DEMB_];
__device__ float g_rnorm[BB * NSEQ];
__device__ float g_vals[BB * NSEQ * KTOP];
__device__ int   g_idx[BB * NSEQ * KTOP];

// ---------------- bf16 helpers ----------------
__device__ __forceinline__ unsigned pack2(float a, float b) {
    __nv_bfloat162 v = __floats2bfloat162_rn(a, b);
    return *(unsigned*)&v;
}
__device__ __forceinline__ float bf2f(__nv_bfloat16 h) { return __bfloat162float(h); }

// split x -> hi (bf16) + lo (bf16 of residual)
__device__ __forceinline__ void split2(float x, float& h, float& l) {
    __nv_bfloat16 hb = __float2bfloat16_rn(x);
    h = __bfloat162float(hb);
    l = x - h;
}

__device__ __forceinline__ void mma_bf16(float* d, const unsigned* a, const unsigned* b) {
    asm volatile(
        "mma.sync.aligned.m16n8k16.row.col.f32.bf16.bf16.f32 "
        "{%0,%1,%2,%3}, {%4,%5,%6,%7}, {%8,%9}, {%0,%1,%2,%3};"
        : "+f"(d[0]), "+f"(d[1]), "+f"(d[2]), "+f"(d[3])
        : "r"(a[0]), "r"(a[1]), "r"(a[2]), "r"(a[3]), "r"(b[0]), "r"(b[1]));
}

// ---------------- embedding gather ----------------
__global__ void k_embed(const int* __restrict__ ids, const float* __restrict__ emb) {
    int row = blockIdx.x;
    int id = ids[row];
    const float4* src = (const float4*)(emb + (size_t)id * DEMB_);
    float4* dst = (float4*)(g_x + (size_t)row * DD);
    dst[threadIdx.x] = src[threadIdx.x];
}

// ---------------- entity masked-mean pooling ----------------
__global__ void k_entpool(const float* __restrict__ e1, const float* __restrict__ e2) {
    int b = blockIdx.x;
    int t = threadIdx.x;
    __shared__ float m1[NSEQ], m2[NSEQ];
    __shared__ float c1s, c2s;
    m1[t] = e1[b * NSEQ + t];
    m2[t] = e2[b * NSEQ + t];
    __syncthreads();
    if (t == 0) {
        float a = 0.f, c = 0.f;
        for (int n = 0; n < NSEQ; n++) { a += m1[n]; c += m2[n]; }
        c1s = a; c2s = c;
    }
    __syncthreads();
    float s1 = 0.f, s2 = 0.f;
    const float* xb = g_x + (size_t)b * NSEQ * DD;
    for (int n = 0; n < NSEQ; n++) {
        float v = xb[(size_t)n * DD + t];
        s1 += v * m1[n];
        s2 += v * m2[n];
    }
    g_entcat[b * 512 + t]       = s1 / (c1s + 1e-13f);
    g_entcat[b * 512 + 256 + t] = s2 / (c2s + 1e-13f);
}

// ---------------- ent = entcat @ ep_w + ep_b, broadcast (coalesced stores) ----------------
__global__ void k_entproj(const float* __restrict__ ep_w, const float* __restrict__ ep_b) {
    int b = blockIdx.x;
    int j = threadIdx.x;
    __shared__ float ec[512];
    __shared__ float accs[256];
    ec[j]       = g_entcat[b * 512 + j];
    ec[j + 256] = g_entcat[b * 512 + j + 256];
    __syncthreads();
    float acc = ep_b[j];
    for (int d = 0; d < 512; d++) acc += ec[d] * ep_w[d * DEMB_ + j];
    accs[j] = acc;
    __syncthreads();
    float* xb = g_x + (size_t)b * NSEQ * DD;
    for (int i = j; i < NSEQ * 256; i += 256) {
        int n = i >> 8, c = i & 255;
        xb[(size_t)n * DD + DEMB_ + c] = accs[c];
    }
}

// ---------------- per-row inverse L2 norm (one warp per row) ----------------
__global__ void k_norms() {
    int row = blockIdx.x * 8 + (threadIdx.x >> 5);
    int lane = threadIdx.x & 31;
    const float4* xr = (const float4*)(g_x + (size_t)row * DD);
    float ss = 0.f;
    #pragma unroll
    for (int q = 0; q < 4; q++) {
        float4 v = xr[lane + q * 32];
        ss += v.x * v.x + v.y * v.y + v.z * v.z + v.w * v.w;
    }
    #pragma unroll
    for (int o = 16; o > 0; o >>= 1) ss += __shfl_xor_sync(0xffffffffu, ss, o);
    if (lane == 0) g_rnorm[row] = 1.f / fmaxf(sqrtf(ss), 1e-12f);
}

// ---------------- sim = (x @ x^T) * rn_i * rn_j via 2-split bf16 MMA ----------------
// tile 128x64, 8 warps (4x2), warp tile 32x32, KTILE=16 (one m16n8k16 per tile)
__global__ __launch_bounds__(256) void k_sim_mma() {
    int b = blockIdx.z;
    int i0 = blockIdx.y * 128, j0 = blockIdx.x * 64;
    const float* A = g_x + (size_t)b * NSEQ * DD;
    __shared__ unsigned Ah[8][136], Al[8][136];   // [kpair][row]
    __shared__ unsigned Bh[8][72],  Bl[8][72];    // [kpair][n]
    __shared__ float rnI[128], rnJ[64];
    int t = threadIdx.x;
    int lane = t & 31, wid = t >> 5;
    int wm = wid >> 1, wn = wid & 1;
    int g = lane >> 2, tig = lane & 3;
    if (t < 128) rnI[t] = g_rnorm[b * NSEQ + i0 + t];
    else if (t < 192) rnJ[t - 128] = g_rnorm[b * NSEQ + j0 + t - 128];
    float acc[2][4][4];
    #pragma unroll
    for (int a = 0; a < 2; a++)
        #pragma unroll
        for (int n = 0; n < 4; n++)
            #pragma unroll
            for (int e = 0; e < 4; e++) acc[a][n][e] = 0.f;

    for (int kk = 0; kk < DD; kk += 16) {
        #pragma unroll
        for (int q = 0; q < 2; q++) {
            int idx = t + q * 256;
            int row = idx >> 2, j = idx & 3;
            float4 xv = *(const float4*)(A + (size_t)(i0 + row) * DD + kk + j * 4);
            float hx, lx, hy, ly, hz, lz, hw, lw;
            split2(xv.x, hx, lx); split2(xv.y, hy, ly);
            split2(xv.z, hz, lz); split2(xv.w, hw, lw);
            Ah[2 * j][row]     = pack2(hx, hy);
            Ah[2 * j + 1][row] = pack2(hz, hw);
            Al[2 * j][row]     = pack2(lx, ly);
            Al[2 * j + 1][row] = pack2(lz, lw);
        }
        {
            int n = t >> 2, j = t & 3;
            float4 xv = *(const float4*)(A + (size_t)(j0 + n) * DD + kk + j * 4);
            float hx, lx, hy, ly, hz, lz, hw, lw;
            split2(xv.x, hx, lx); split2(xv.y, hy, ly);
            split2(xv.z, hz, lz); split2(xv.w, hw, lw);
            Bh[2 * j][n]     = pack2(hx, hy);
            Bh[2 * j + 1][n] = pack2(hz, hw);
            Bl[2 * j][n]     = pack2(lx, ly);
            Bl[2 * j + 1][n] = pack2(lz, lw);
        }
        __syncthreads();
        unsigned ah[2][4], al[2][4], bh[4][2], bl[4][2];
        #pragma unroll
        for (int mt = 0; mt < 2; mt++) {
            int r = wm * 32 + mt * 16 + g;
            ah[mt][0] = Ah[tig][r];     ah[mt][1] = Ah[tig][r + 8];
            ah[mt][2] = Ah[tig + 4][r]; ah[mt][3] = Ah[tig + 4][r + 8];
            al[mt][0] = Al[tig][r];     al[mt][1] = Al[tig][r + 8];
            al[mt][2] = Al[tig + 4][r]; al[mt][3] = Al[tig + 4][r + 8];
        }
        #pragma unroll
        for (int nt = 0; nt < 4; nt++) {
            int n = wn * 32 + nt * 8 + g;
            bh[nt][0] = Bh[tig][n]; bh[nt][1] = Bh[tig + 4][n];
            bl[nt][0] = Bl[tig][n]; bl[nt][1] = Bl[tig + 4][n];
        }
        #pragma unroll
        for (int mt = 0; mt < 2; mt++)
            #pragma unroll
            for (int nt = 0; nt < 4; nt++) {
                mma_bf16(acc[mt][nt], ah[mt], bh[nt]);
                mma_bf16(acc[mt][nt], ah[mt], bl[nt]);
                mma_bf16(acc[mt][nt], al[mt], bh[nt]);
            }
        __syncthreads();
    }
    float* C = g_adj + (size_t)b * NSEQ * NSEQ;
    #pragma unroll
    for (int mt = 0; mt < 2; mt++)
        #pragma unroll
        for (int nt = 0; nt < 4; nt++) {
            int rl = wm * 32 + mt * 16 + g;
            int cl = wn * 32 + nt * 8 + tig * 2;
            int r = i0 + rl, c = j0 + cl;
            float s0 = rnI[rl] * rnJ[cl], s1 = rnI[rl] * rnJ[cl + 1];
            float s2 = rnI[rl + 8] * rnJ[cl], s3 = rnI[rl + 8] * rnJ[cl + 1];
            C[(size_t)r * NSEQ + c]           = acc[mt][nt][0] * s0;
            C[(size_t)r * NSEQ + c + 1]       = acc[mt][nt][1] * s1;
            C[(size_t)(r + 8) * NSEQ + c]     = acc[mt][nt][2] * s2;
            C[(size_t)(r + 8) * NSEQ + c + 1] = acc[mt][nt][3] * s3;
        }
}

// ---------------- top-8 with coalesced smem staging ----------------
__global__ __launch_bounds__(128) void k_topk() {
    __shared__ float sh[128][36];
    int rb = blockIdx.x * 128;
    int t = threadIdx.x;
    float v[KTOP]; int id[KTOP];
    #pragma unroll
    for (int k = 0; k < KTOP; k++) { v[k] = -1e30f; id[k] = -1; }
    for (int ch = 0; ch < 8; ch++) {
        __syncthreads();
        for (int q = t; q < 1024; q += 128) {
            int row = q >> 3, c4 = q & 7;
            float4 x = *(const float4*)(g_adj + (size_t)(rb + row) * NSEQ + ch * 32 + c4 * 4);
            *(float4*)&sh[row][c4 * 4] = x;
        }
        __syncthreads();
        #pragma unroll 4
        for (int c = 0; c < 32; c++) {
            float x = sh[t][c];
            if (x > v[KTOP - 1]) {
                int m = ch * 32 + c;
                int p = KTOP - 1;
                while (p > 0 && v[p - 1] < x) { v[p] = v[p - 1]; id[p] = id[p - 1]; p--; }
                v[p] = x; id[p] = m;
            }
        }
    }
    int row = rb + t;
    #pragma unroll
    for (int k = 0; k < KTOP; k++) {
        g_vals[row * KTOP + k] = v[k];
        g_idx[row * KTOP + k]  = id[k];
    }
}

// ---------------- zero adj ----------------
__global__ void k_zero_adj() {
    int i = blockIdx.x * blockDim.x + threadIdx.x;
    int n4 = BB * NSEQ * NSEQ / 4;
    if (i < n4) ((float4*)g_adj)[i] = make_float4(0.f, 0.f, 0.f, 0.f);
}

// ---------------- adj = (mask + mask^T)/2 via atomic scatter ----------------
__global__ void k_adjbuild() {
    int t = blockIdx.x * blockDim.x + threadIdx.x;
    if (t >= BB * NSEQ * KTOP) return;
    int row = t / KTOP;
    int b = row / NSEQ, n = row % NSEQ;
    float v = 0.5f * g_vals[t];
    int m = g_idx[t];
    float* adjb = g_adj + (size_t)b * NSEQ * NSEQ;
    atomicAdd(&adjb[n * NSEQ + m], v);
    atomicAdd(&adjb[m * NSEQ + n], v);
}

// ---------------- xqw = x @ sign(W) * 0.1 via 2-split bf16 MMA (W exact in bf16) ----------------
__global__ __launch_bounds__(256) void k_xqw_mma(const float* __restrict__ W) {
    int i0 = blockIdx.y * 128, j0 = blockIdx.x * 64;
    __shared__ unsigned Ah[8][136], Al[8][136];
    __shared__ unsigned Bq[8][72];
    int t = threadIdx.x;
    int lane = t & 31, wid = t >> 5;
    int wm = wid >> 1, wn = wid & 1;
    int g = lane >> 2, tig = lane & 3;
    float acc[2][4][4];
    #pragma unroll
    for (int a = 0; a < 2; a++)
        #pragma unroll
        for (int n = 0; n < 4; n++)
            #pragma unroll
            for (int e = 0; e < 4; e++) acc[a][n][e] = 0.f;

    for (int kk = 0; kk < DD; kk += 16) {
        #pragma unroll
        for (int q = 0; q < 2; q++) {
            int idx = t + q * 256;
            int row = idx >> 2, j = idx & 3;
            float4 xv = *(const float4*)(g_x + (size_t)(i0 + row) * DD + kk + j * 4);
            float hx, lx, hy, ly, hz, lz, hw, lw;
            split2(xv.x, hx, lx); split2(xv.y, hy, ly);
            split2(xv.z, hz, lz); split2(xv.w, hw, lw);
            Ah[2 * j][row]     = pack2(hx, hy);
            Ah[2 * j + 1][row] = pack2(hz, hw);
            Al[2 * j][row]     = pack2(lx, ly);
            Al[2 * j + 1][row] = pack2(lz, lw);
        }
        {
            int k = t >> 4, n4 = t & 15;
            float4 w = *(const float4*)(W + (size_t)(kk + k) * DD + j0 + n4 * 4);
            float q0 = (w.x > 0.1f) ? 1.f : ((w.x < -0.1f) ? -1.f : 0.f);
            float q1 = (w.y > 0.1f) ? 1.f : ((w.y < -0.1f) ? -1.f : 0.f);
            float q2 = (w.z > 0.1f) ? 1.f : ((w.z < -0.1f) ? -1.f : 0.f);
            float q3 = (w.w > 0.1f) ? 1.f : ((w.w < -0.1f) ? -1.f : 0.f);
            // write bf16 halves: element (k, n) -> Bq[k>>1][n], half (k&1)
            __nv_bfloat16* h16 = (__nv_bfloat16*)&Bq[k >> 1][0];
            int hoff = (k & 1);
            h16[(n4 * 4 + 0) * 2 + hoff] = __float2bfloat16_rn(q0);
            h16[(n4 * 4 + 1) * 2 + hoff] = __float2bfloat16_rn(q1);
            h16[(n4 * 4 + 2) * 2 + hoff] = __float2bfloat16_rn(q2);
            h16[(n4 * 4 + 3) * 2 + hoff] = __float2bfloat16_rn(q3);
        }
        __syncthreads();
        unsigned ah[2][4], al[2][4], bq[4][2];
        #pragma unroll
        for (int mt = 0; mt < 2; mt++) {
            int r = wm * 32 + mt * 16 + g;
            ah[mt][0] = Ah[tig][r];     ah[mt][1] = Ah[tig][r + 8];
            ah[mt][2] = Ah[tig + 4][r]; ah[mt][3] = Ah[tig + 4][r + 8];
            al[mt][0] = Al[tig][r];     al[mt][1] = Al[tig][r + 8];
            al[mt][2] = Al[tig + 4][r]; al[mt][3] = Al[tig + 4][r + 8];
        }
        #pragma unroll
        for (int nt = 0; nt < 4; nt++) {
            int n = wn * 32 + nt * 8 + g;
            bq[nt][0] = Bq[tig][n]; bq[nt][1] = Bq[tig + 4][n];
        }
        #pragma unroll
        for (int mt = 0; mt < 2; mt++)
            #pragma unroll
            for (int nt = 0; nt < 4; nt++) {
                mma_bf16(acc[mt][nt], ah[mt], bq[nt]);
                mma_bf16(acc[mt][nt], al[mt], bq[nt]);
            }
        __syncthreads();
    }
    #pragma unroll
    for (int mt = 0; mt < 2; mt++)
        #pragma unroll
        for (int nt = 0; nt < 4; nt++) {
            int r = i0 + wm * 32 + mt * 16 + g;
            int c = j0 + wn * 32 + nt * 8 + tig * 2;
            g_xn[(size_t)r * DD + c]           = 0.1f * acc[mt][nt][0];
            g_xn[(size_t)r * DD + c + 1]       = 0.1f * acc[mt][nt][1];
            g_xn[(size_t)(r + 8) * DD + c]     = 0.1f * acc[mt][nt][2];
            g_xn[(size_t)(r + 8) * DD + c + 1] = 0.1f * acc[mt][nt][3];
        }
}

// ---------------- gcn_out = relu(adj @ y + bias) via 2-split bf16 MMA ----------------
__global__ __launch_bounds__(256) void k_gcn_mma(const float* __restrict__ bias) {
    int b = blockIdx.z;
    int i0 = blockIdx.y * 128, j0 = blockIdx.x * 64;
    const float* A = g_adj + (size_t)b * NSEQ * NSEQ;
    const float* Y = g_xn + (size_t)b * NSEQ * DD;
    __shared__ unsigned Ah[8][136], Al[8][136];
    __shared__ unsigned Bh[8][72], Bl[8][72];
    int t = threadIdx.x;
    int lane = t & 31, wid = t >> 5;
    int wm = wid >> 1, wn = wid & 1;
    int g = lane >> 2, tig = lane & 3;
    float acc[2][4][4];
    #pragma unroll
    for (int a = 0; a < 2; a++)
        #pragma unroll
        for (int n = 0; n < 4; n++)
            #pragma unroll
            for (int e = 0; e < 4; e++) acc[a][n][e] = 0.f;

    for (int kk = 0; kk < NSEQ; kk += 16) {
        #pragma unroll
        for (int q = 0; q < 2; q++) {
            int idx = t + q * 256;
            int row = idx >> 2, j = idx & 3;
            float4 xv = *(const float4*)(A + (size_t)(i0 + row) * NSEQ + kk + j * 4);
            float hx, lx, hy, ly, hz, lz, hw, lw;
            split2(xv.x, hx, lx); split2(xv.y, hy, ly);
            split2(xv.z, hz, lz); split2(xv.w, hw, lw);
            Ah[2 * j][row]     = pack2(hx, hy);
            Ah[2 * j + 1][row] = pack2(hz, hw);
            Al[2 * j][row]     = pack2(lx, ly);
            Al[2 * j + 1][row] = pack2(lz, lw);
        }
        {
            int k = t >> 4, n4 = t & 15;
            float4 yv = *(const float4*)(Y + (size_t)(kk + k) * DD + j0 + n4 * 4);
            float f[4] = {yv.x, yv.y, yv.z, yv.w};
            __nv_bfloat16* h16 = (__nv_bfloat16*)&Bh[k >> 1][0];
            __nv_bfloat16* l16 = (__nv_bfloat16*)&Bl[k >> 1][0];
            int hoff = (k & 1);
            #pragma unroll
            for (int e = 0; e < 4; e++) {
                float h, l;
                split2(f[e], h, l);
                h16[(n4 * 4 + e) * 2 + hoff] = __float2bfloat16_rn(h);
                l16[(n4 * 4 + e) * 2 + hoff] = __float2bfloat16_rn(l);
            }
        }
        __syncthreads();
        unsigned ah[2][4], al[2][4], bh[4][2], bl[4][2];
        #pragma unroll
        for (int mt = 0; mt < 2; mt++) {
            int r = wm * 32 + mt * 16 + g;
            ah[mt][0] = Ah[tig][r];     ah[mt][1] = Ah[tig][r + 8];
            ah[mt][2] = Ah[tig + 4][r]; ah[mt][3] = Ah[tig + 4][r + 8];
            al[mt][0] = Al[tig][r];     al[mt][1] = Al[tig][r + 8];
            al[mt][2] = Al[tig + 4][r]; al[mt][3] = Al[tig + 4][r + 8];
        }
        #pragma unroll
        for (int nt = 0; nt < 4; nt++) {
            int n = wn * 32 + nt * 8 + g;
            bh[nt][0] = Bh[tig][n]; bh[nt][1] = Bh[tig + 4][n];
            bl[nt][0] = Bl[tig][n]; bl[nt][1] = Bl[tig + 4][n];
        }
        #pragma unroll
        for (int mt = 0; mt < 2; mt++)
            #pragma unroll
            for (int nt = 0; nt < 4; nt++) {
                mma_bf16(acc[mt][nt], ah[mt], bh[nt]);
                mma_bf16(acc[mt][nt], ah[mt], bl[nt]);
                mma_bf16(acc[mt][nt], al[mt], bh[nt]);
            }
        __syncthreads();
    }
    float* C = g_comb + (size_t)b * NSEQ * DD;
    #pragma unroll
    for (int mt = 0; mt < 2; mt++)
        #pragma unroll
        for (int nt = 0; nt < 4; nt++) {
            int r = i0 + wm * 32 + mt * 16 + g;
            int c = j0 + wn * 32 + nt * 8 + tig * 2;
            float b0 = bias[c], b1 = bias[c + 1];
            C[(size_t)r * DD + c]           = fmaxf(acc[mt][nt][0] + b0, 0.f);
            C[(size_t)r * DD + c + 1]       = fmaxf(acc[mt][nt][1] + b1, 0.f);
            C[(size_t)(r + 8) * DD + c]     = fmaxf(acc[mt][nt][2] + b0, 0.f);
            C[(size_t)(r + 8) * DD + c + 1] = fmaxf(acc[mt][nt][3] + b1, 0.f);
        }
}

// ---------------- fused conv: 32x64 tile, 2-channel chunks, 4x2 register blocking ----------------
__global__ __launch_bounds__(256) void k_conv(const float* __restrict__ c1w, const float* __restrict__ c1b,
                                              const float* __restrict__ bng, const float* __restrict__ bnb,
                                              const float* __restrict__ c2w, const float* __restrict__ c2b) {
    __shared__ float xt[36][69];
    __shared__ float hs[2][36][69];
    __shared__ float w1s[32][9], w2s[32][9], scs[32], tcs[32];
    int b = blockIdx.z;
    int oy0 = blockIdx.y * 32, ox0 = blockIdx.x * 64;
    int t = threadIdx.x;
    if (t < 32) {
        float s = bng[t] * rsqrtf(1.f + 1e-5f);
        scs[t] = s;
        tcs[t] = c1b[t] * s + bnb[t];
    }
    for (int i = t; i < 288; i += 256) {
        w1s[i / 9][i % 9] = c1w[i];
        w2s[i / 9][i % 9] = c2w[i];
    }
    const float* xb = g_x + (size_t)b * NSEQ * DD;
    for (int i = t; i < 36 * 68; i += 256) {
        int r = i / 68, c = i % 68;
        int gy = oy0 - 2 + r, gx = ox0 - 2 + c;
        xt[r][c] = (gy >= 0 && gy < NSEQ && gx >= 0 && gx < DD) ? xb[(size_t)gy * DD + gx] : 0.f;
    }
    __syncthreads();

    int rg = t & 7, cp = t >> 3;
    int oy = rg * 4, ox = cp * 2;
    float acc[4][2] = {};

    for (int chunk = 0; chunk < 16; chunk++) {
        for (int tau = t; tau < 2 * 9 * 33; tau += 256) {
            int g2 = tau % 9;
            int cloc = (tau / 9) & 1;
            int q = tau / 18;
            int cg = chunk * 2 + cloc;
            int ly0 = g2 * 4, lx0 = q * 2;
            float w[9];
            #pragma unroll
            for (int u = 0; u < 9; u++) w[u] = w1s[cg][u];
            float sc = scs[cg], tc = tcs[cg];
            float hb[6][4];
            #pragma unroll
            for (int yy = 0; yy < 6; yy++) {
                int xr = ly0 + yy;
                bool ok = xr < 36;
                #pragma unroll
                for (int xx = 0; xx < 4; xx++)
                    hb[yy][xx] = ok ? xt[xr][lx0 + xx] : 0.f;
            }
            #pragma unroll
            for (int yy = 0; yy < 4; yy++) {
                int ly = ly0 + yy;
                int gy = oy0 - 1 + ly;
                #pragma unroll
                for (int xx = 0; xx < 2; xx++) {
                    int gx = ox0 - 1 + lx0 + xx;
                    float a = 0.f;
                    #pragma unroll
                    for (int dy = 0; dy < 3; dy++)
                        #pragma unroll
                        for (int dx = 0; dx < 3; dx++)
                            a += hb[yy + dy][xx + dx] * w[dy * 3 + dx];
                    float hv = (gy >= 0 && gy < NSEQ && gx >= 0 && gx < DD)
                                   ? fmaxf(a * sc + tc, 0.f) : 0.f;
                    hs[cloc][ly][lx0 + xx] = hv;
                }
            }
        }
        __syncthreads();
        #pragma unroll
        for (int cloc = 0; cloc < 2; cloc++) {
            int cg = chunk * 2 + cloc;
            float w[9];
            #pragma unroll
            for (int u = 0; u < 9; u++) w[u] = w2s[cg][u];
            float hb[6][4];
            #pragma unroll
            for (int yy = 0; yy < 6; yy++)
                #pragma unroll
                for (int xx = 0; xx < 4; xx++)
                    hb[yy][xx] = hs[cloc][oy + yy][ox + xx];
            #pragma unroll
            for (int yy = 0; yy < 4; yy++)
                #pragma unroll
                for (int xx = 0; xx < 2; xx++)
                    #pragma unroll
                    for (int dy = 0; dy < 3; dy++)
                        #pragma unroll
                        for (int dx = 0; dx < 3; dx++)
                            acc[yy][xx] += hb[yy + dy][xx + dx] * w[dy * 3 + dx];
        }
        __syncthreads();
    }
    float bias = c2b[0];
    #pragma unroll
    for (int yy = 0; yy < 4; yy++)
        #pragma unroll
        for (int xx = 0; xx < 2; xx++)
            hs[0][oy + yy][ox + xx] = acc[yy][xx] + bias;
    __syncthreads();
    float* cb = g_comb + (size_t)b * NSEQ * DD;
    for (int i = t; i < 32 * 64; i += 256) {
        int r = i >> 6, c = i & 63;
        cb[(size_t)(oy0 + r) * DD + ox0 + c] += hs[0][r][c];
    }
}

// ---------------- gate + residual mix ----------------
__global__ void k_gate(const float* __restrict__ gw, const float* __restrict__ gb) {
    int row = blockIdx.x;
    int t = threadIdx.x;
    size_t off = (size_t)row * DD;
    float x1 = g_x[off + t],    x2 = g_x[off + t + 256];
    float c1 = g_comb[off + t], c2 = g_comb[off + t + 256];
    float p = x1 * gw[t] + x2 * gw[t + 256] + c1 * gw[512 + t] + c2 * gw[768 + t];
    #pragma unroll
    for (int o = 16; o > 0; o >>= 1) p += __shfl_xor_sync(0xffffffffu, p, o);
    __shared__ float ws[8];
    if ((t & 31) == 0) ws[t >> 5] = p;
    __syncthreads();
    float tot = ws[0] + ws[1] + ws[2] + ws[3] + ws[4] + ws[5] + ws[6] + ws[7];
    float g = 1.f / (1.f + expf(-(tot + gb[0])));
    g_x[off + t]       = g * x1 + (1.f - g) * c1;
    g_x[off + t + 256] = g * x2 + (1.f - g) * c2;
}

// ---------------- mean pool + classifier ----------------
__global__ void k_cls(const float* __restrict__ w1, const float* __restrict__ b1,
                      const float* __restrict__ w2, const float* __restrict__ b2,
                      float* __restrict__ out) {
    int b = blockIdx.x;
    int t = threadIdx.x;
    __shared__ float pooled[512], h1[512];
    float s = 0.f;
    const float* xb = g_x + (size_t)b * NSEQ * DD;
    for (int n = 0; n < NSEQ; n++) s += xb[(size_t)n * DD + t];
    pooled[t] = s * (1.f / NSEQ);
    __syncthreads();
    float a = b1[t];
    for (int d = 0; d < 512; d++) a += pooled[d] * w1[d * 512 + t];
    h1[t] = fmaxf(a, 0.f);
    __syncthreads();
    if (t < LABELS_) {
        float a2 = b2[t];
        for (int d = 0; d < 512; d++) a2 += h1[d] * w2[d * LABELS_ + t];
        out[b * LABELS_ + t] = a2;
    }
}

// ---------------- launch ----------------
extern "C" void kernel_launch(void* const* d_in, const int* in_sizes, int n_in,
                              void* d_out, int out_size) {
    const int*   ids   = (const int*)  d_in[0];
    const float* e1    = (const float*)d_in[1];
    const float* e2    = (const float*)d_in[2];
    const float* emb   = (const float*)d_in[3];
    const float* ep_w  = (const float*)d_in[4];
    const float* ep_b  = (const float*)d_in[5];
    const float* gcn_w = (const float*)d_in[6];
    const float* gcn_b = (const float*)d_in[7];
    const float* c1w   = (const float*)d_in[8];
    const float* c1b   = (const float*)d_in[9];
    const float* bng   = (const float*)d_in[10];
    const float* bnb   = (const float*)d_in[11];
    const float* c2w   = (const float*)d_in[12];
    const float* c2b   = (const float*)d_in[13];
    const float* gw    = (const float*)d_in[14];
    const float* gb    = (const float*)d_in[15];
    const float* clw1  = (const float*)d_in[16];
    const float* clb1  = (const float*)d_in[17];
    const float* clw2  = (const float*)d_in[18];
    const float* clb2  = (const float*)d_in[19];
    float* out = (float*)d_out;

    k_embed<<<BB * NSEQ, 64>>>(ids, emb);
    k_entpool<<<BB, 256>>>(e1, e2);
    k_entproj<<<BB, 256>>>(ep_w, ep_b);

    for (int i = 0; i < 2; i++) {
        k_norms<<<BB * NSEQ / 8, 256>>>();
        k_sim_mma<<<dim3(4, 2, BB), 256>>>();
        k_topk<<<BB * NSEQ / 128, 128>>>();
        k_zero_adj<<<(BB * NSEQ * NSEQ / 4 + 255) / 256, 256>>>();
        k_adjbuild<<<(BB * NSEQ * KTOP + 255) / 256, 256>>>();
        k_xqw_mma<<<dim3(8, 256), 256>>>(gcn_w + (size_t)i * DD * DD);
        k_gcn_mma<<<dim3(8, 2, BB), 256>>>(gcn_b + i * DD);
        k_conv<<<dim3(8, 8, BB), 256>>>(c1w + i * 288, c1b + i * 32,
                                        bng + i * 32, bnb + i * 32,
                                        c2w + i * 288, c2b + i);
        k_gate<<<BB * NSEQ, 256>>>(gw, gb);
    }
    k_cls<<<BB, 512>>>(clw1, clb1, clw2, clb2, out);
}